// round 6
// baseline (speedup 1.0000x reference)
#include <cuda_runtime.h>
#include <math.h>
#include <stdint.h>

// ---------------- problem constants ----------------
#define B_    16
#define NTOK  196
#define SPLN  98
#define N_    491          // 1 + 98*4 + 98
#define C_    768
#define HM_   3072
#define H_    12
#define D_    64
#define L_    4
#define M_ROWS (B_*N_)     // 7856

// weight sizes
#define SW_SZ   (C_*4*C_)
#define QW_SZ   (C_*3*C_)
#define PW_SZ   (C_*C_)
#define F1_SZ   (C_*HM_)
#define F2_SZ   (HM_*C_)

// ---------------- device scratch ----------------
__device__ float g_x   [B_*N_*C_];
__device__ float g_h   [B_*N_*C_];
__device__ float g_qkv [B_*N_*3*C_];
__device__ float g_o   [B_*N_*C_];
__device__ float g_mlp [B_*N_*HM_];
__device__ float g_tok [B_*SPLN*C_];
__device__ int   g_ord [B_*NTOK];
__device__ float g_glb [B_*(N_-1)];
__device__ float g_cls [B_*(N_-1)];
// tf32-rounded weights
__device__ float g_wsplit[SW_SZ];
__device__ float g_wqkv  [L_*QW_SZ];
__device__ float g_wproj [L_*PW_SZ];
__device__ float g_wfc1  [L_*F1_SZ];
__device__ float g_wfc2  [L_*F2_SZ];

// ---------------- helpers ----------------
__device__ __forceinline__ uint32_t smem_u32(const void* p) {
    uint32_t a;
    asm("{ .reg .u64 t; cvta.to.shared.u64 t, %1; cvt.u32.u64 %0, t; }" : "=r"(a) : "l"(p));
    return a;
}
__device__ __forceinline__ uint32_t f2tf32(float x) {
    uint32_t r;
    asm("cvt.rna.tf32.f32 %0, %1;" : "=r"(r) : "f"(x));
    return r;
}
__device__ __forceinline__ float rndtf32(float x) { return __uint_as_float(f2tf32(x)); }

__device__ __forceinline__ void mma_tf32(float& c0, float& c1, float& c2, float& c3,
                                         uint32_t a0, uint32_t a1, uint32_t a2, uint32_t a3,
                                         uint32_t b0, uint32_t b1) {
    asm volatile("mma.sync.aligned.m16n8k8.row.col.f32.tf32.tf32.f32 "
                 "{%0,%1,%2,%3}, {%4,%5,%6,%7}, {%8,%9}, {%0,%1,%2,%3};"
                 : "+f"(c0), "+f"(c1), "+f"(c2), "+f"(c3)
                 : "r"(a0), "r"(a1), "r"(a2), "r"(a3), "r"(b0), "r"(b1));
}
__device__ __forceinline__ void cp16(uint32_t dst, const float* src, int sz) {
    asm volatile("cp.async.cg.shared.global [%0], [%1], 16, %2;"
                 :: "r"(dst), "l"(src), "r"(sz) : "memory");
}
#define CP_COMMIT() asm volatile("cp.async.commit_group;" ::: "memory")
#define CP_WAIT1()  asm volatile("cp.async.wait_group 1;" ::: "memory")
#define CP_WAIT0()  asm volatile("cp.async.wait_group 0;" ::: "memory")

// ---------------- weight convert ----------------
__global__ void wconv_kernel(const float* __restrict__ src, float* __restrict__ dst, int n) {
    int stride = gridDim.x * blockDim.x;
    for (int i = blockIdx.x*blockDim.x + threadIdx.x; i < n; i += stride)
        dst[i] = rndtf32(src[i]);
}

// ---------------- sort ----------------
__global__ void sort_kernel(const float* __restrict__ attn) {
    __shared__ float sv[256];
    __shared__ int   si[256];
    int b = blockIdx.x, t = threadIdx.x;
    sv[t] = (t < NTOK) ? attn[b*NTOK + t] : -INFINITY;
    si[t] = t;
    __syncthreads();
    for (int k = 2; k <= 256; k <<= 1) {
        for (int j = k >> 1; j > 0; j >>= 1) {
            int ix = t ^ j;
            if (ix > t) {
                float v1 = sv[t], v2 = sv[ix];
                int   i1 = si[t], i2 = si[ix];
                bool before = (v1 > v2) || (v1 == v2 && i1 < i2);
                bool doswap = ((t & k) == 0) ? (!before) : before;
                if (doswap) { sv[t]=v2; sv[ix]=v1; si[t]=i2; si[ix]=i1; }
            }
            __syncthreads();
        }
    }
    if (t < NTOK) g_ord[b*NTOK + t] = si[t];
}

// ---------------- gather ----------------
__global__ void gather_kernel(const float* __restrict__ xin) {
    int blk = blockIdx.x;
    int b = blk / 197, r = blk % 197;
    int t = threadIdx.x;
    const float* srow;
    float* drow;
    bool rnd = false;
    if (r == 0) {
        srow = xin + (size_t)b*197*C_;
        drow = g_x + (size_t)b*N_*C_;
    } else if (r <= SPLN) {
        int i = r - 1;
        int ord = g_ord[b*NTOK + i];
        srow = xin + ((size_t)b*197 + 1 + ord)*C_;
        drow = g_tok + ((size_t)b*SPLN + i)*C_;
        rnd = true;
    } else {
        int i = r - 1 - SPLN;
        int ord = g_ord[b*NTOK + SPLN + i];
        srow = xin + ((size_t)b*197 + 1 + ord)*C_;
        drow = g_x + ((size_t)b*N_ + 1 + SPLN*4 + i)*C_;
    }
    if (rnd) {
        drow[t]       = rndtf32(srow[t]);
        drow[t + 256] = rndtf32(srow[t + 256]);
        drow[t + 512] = rndtf32(srow[t + 512]);
    } else {
        drow[t]       = srow[t];
        drow[t + 256] = srow[t + 256];
        drow[t + 512] = srow[t + 512];
    }
}

__global__ void init_kernel() {
    int i = blockIdx.x*blockDim.x + threadIdx.x;
    if (i < B_*(N_-1)) { g_glb[i] = 0.f; g_cls[i] = 0.f; }
}

// ---------------- mma.sync tf32 GEMM, 256x128 tile, warp 64x64, BK=32, 3-stage cp.async ----
// modes: 0 bias | 1 bias+gelu(erf)+tf32 round | 2 bias+residual | 3 bias + split row-remap
#define BM 256
#define A_STRIDE 36
#define W_STRIDE 136
#define A_FL (BM*A_STRIDE)          // 9216 floats
#define W_FL (32*W_STRIDE)          // 4352 floats
#define BUF_FL (A_FL + W_FL)        // 13568 floats
#define NSTAGE 3
#define GEMM_SMEM (NSTAGE*BUF_FL*4) // 162816 bytes

__global__ __launch_bounds__(256, 1)
void gemm_cp(const float* __restrict__ A, const float* __restrict__ W,
             const float* __restrict__ bias, const float* __restrict__ resid,
             float* __restrict__ out, int M, int N, int K, int mode) {
    extern __shared__ float sm[];
    int tid  = threadIdx.x;
    int m0   = blockIdx.y * BM, n0 = blockIdx.x * 128;
    int warp = tid >> 5, lane = tid & 31;
    int g    = lane >> 2, tig = lane & 3;
    int wm0  = (warp >> 1) * 64;      // 4 warps in M
    int wn0  = (warp & 1) * 64;       // 2 warps in N

    uint32_t sbase = smem_u32(sm);

    float acc[4][8][4];
#pragma unroll
    for (int i = 0; i < 4; i++)
#pragma unroll
        for (int j = 0; j < 8; j++)
#pragma unroll
            for (int c = 0; c < 4; c++) acc[i][j][c] = 0.f;

    int nt = K >> 5;   // K multiple of 32

#define ISSUE_TILE(kc_, buf_) do {                                           \
        uint32_t ab = sbase + (uint32_t)(buf_) * (BUF_FL*4);                 \
        uint32_t wb = ab + A_FL*4;                                           \
        _Pragma("unroll")                                                    \
        for (int it = 0; it < 8; it++) {                                     \
            int chunk = tid + it*256;                                        \
            int row = chunk >> 3, c4 = chunk & 7;                            \
            int gr = m0 + row;                                               \
            int ok = (gr < M);                                               \
            const float* src = A + (size_t)(ok ? gr : 0)*K + (kc_)*32 + c4*4;\
            cp16(ab + row*(A_STRIDE*4) + c4*16, src, ok ? 16 : 0);           \
        }                                                                    \
        _Pragma("unroll")                                                    \
        for (int it = 0; it < 4; it++) {                                     \
            int chunk = tid + it*256;                                        \
            int kr = chunk >> 5, c4 = chunk & 31;                            \
            const float* src = W + (size_t)((kc_)*32 + kr)*N + n0 + c4*4;    \
            cp16(wb + kr*(W_STRIDE*4) + c4*16, src, 16);                     \
        }                                                                    \
        CP_COMMIT();                                                         \
    } while (0)

    ISSUE_TILE(0, 0);
    if (nt > 1) ISSUE_TILE(1, 1);

    for (int kc = 0; kc < nt; kc++) {
        int buf = kc % NSTAGE;
        if (kc == nt - 1) { CP_WAIT0(); } else { CP_WAIT1(); }
        __syncthreads();
        if (kc + 2 < nt) ISSUE_TILE(kc + 2, (kc + 2) % NSTAGE);

        const float* As = sm + buf * BUF_FL;
        const float* Ws = sm + buf * BUF_FL + A_FL;
#pragma unroll
        for (int ks = 0; ks < 4; ks++) {
            int k0 = ks * 8;
            uint32_t a[4][4], b[8][2];
#pragma unroll
            for (int mi = 0; mi < 4; mi++) {
                int mb = wm0 + mi*16 + g;
                a[mi][0] = __float_as_uint(As[mb*A_STRIDE     + k0 + tig]);
                a[mi][1] = __float_as_uint(As[(mb+8)*A_STRIDE + k0 + tig]);
                a[mi][2] = __float_as_uint(As[mb*A_STRIDE     + k0 + tig + 4]);
                a[mi][3] = __float_as_uint(As[(mb+8)*A_STRIDE + k0 + tig + 4]);
            }
#pragma unroll
            for (int ni = 0; ni < 8; ni++) {
                int nb = wn0 + ni*8 + g;
                b[ni][0] = __float_as_uint(Ws[(k0+tig)*W_STRIDE   + nb]);
                b[ni][1] = __float_as_uint(Ws[(k0+tig+4)*W_STRIDE + nb]);
            }
#pragma unroll
            for (int mi = 0; mi < 4; mi++)
#pragma unroll
                for (int ni = 0; ni < 8; ni++)
                    mma_tf32(acc[mi][ni][0], acc[mi][ni][1], acc[mi][ni][2], acc[mi][ni][3],
                             a[mi][0], a[mi][1], a[mi][2], a[mi][3],
                             b[ni][0], b[ni][1]);
        }
    }
#undef ISSUE_TILE

    // epilogue
#pragma unroll
    for (int mi = 0; mi < 4; mi++) {
#pragma unroll
        for (int half = 0; half < 2; half++) {
            int row = m0 + wm0 + mi*16 + g + half*8;
            if (row >= M) continue;
            float* orow;
            if (mode == 3) {
                int bb = row / SPLN, s = row % SPLN;
                orow = out + ((size_t)bb*N_ + 1 + (size_t)s*4)*C_;
            } else {
                orow = out + (size_t)row*N;
            }
            const float* rrow = (mode == 2) ? (resid + (size_t)row*N) : nullptr;
#pragma unroll
            for (int ni = 0; ni < 8; ni++) {
                int col = n0 + wn0 + ni*8 + tig*2;
                float v0 = acc[mi][ni][half*2]     + bias[col];
                float v1 = acc[mi][ni][half*2 + 1] + bias[col+1];
                if (mode == 1) {
                    v0 = 0.5f*v0*(1.0f + erff(v0*0.70710678118654752f));
                    v1 = 0.5f*v1*(1.0f + erff(v1*0.70710678118654752f));
                    v0 = rndtf32(v0);
                    v1 = rndtf32(v1);
                } else if (mode == 2) {
                    v0 += rrow[col];
                    v1 += rrow[col+1];
                }
                *(float2*)(orow + col) = make_float2(v0, v1);
            }
        }
    }
}

// ---------------- layernorm (tf32-rounded output) ----------------
__global__ __launch_bounds__(256)
void ln_kernel(const float* __restrict__ in, float* __restrict__ out,
               const float* __restrict__ gamma, const float* __restrict__ beta) {
    int row = blockIdx.x, t = threadIdx.x;
    const float* xr = in + (size_t)row * C_;
    float v0 = xr[t], v1 = xr[t+256], v2 = xr[t+512];
    __shared__ float red[8];
    float s = v0 + v1 + v2;
#pragma unroll
    for (int o = 16; o; o >>= 1) s += __shfl_xor_sync(~0u, s, o);
    if ((t & 31) == 0) red[t >> 5] = s;
    __syncthreads();
    float tot = 0.f;
#pragma unroll
    for (int i = 0; i < 8; i++) tot += red[i];
    float mean = tot * (1.0f / C_);
    __syncthreads();
    float d0 = v0 - mean, d1 = v1 - mean, d2 = v2 - mean;
    float s2 = d0*d0 + d1*d1 + d2*d2;
#pragma unroll
    for (int o = 16; o; o >>= 1) s2 += __shfl_xor_sync(~0u, s2, o);
    if ((t & 31) == 0) red[t >> 5] = s2;
    __syncthreads();
    float tot2 = 0.f;
#pragma unroll
    for (int i = 0; i < 8; i++) tot2 += red[i];
    float inv = rsqrtf(tot2 * (1.0f / C_) + 1e-6f);
    float* orow = out + (size_t)row * C_;
    orow[t]       = rndtf32(d0 * inv * gamma[t]       + beta[t]);
    orow[t + 256] = rndtf32(d1 * inv * gamma[t + 256] + beta[t + 256]);
    orow[t + 512] = rndtf32(d2 * inv * gamma[t + 512] + beta[t + 512]);
}

// ---------------- flash attention (tf32 mma), 128 q-rows per CTA ----------------
#define FA_SMEM 141312
__global__ __launch_bounds__(256)
void flash_attn(const float* __restrict__ qkv, float* __restrict__ obuf) {
    extern __shared__ float sf[];
    float* Qs  = sf;
    float* KsB = sf + 8704;
    float* VsB = sf + 17408;
    float* Ps  = sf + 26624;

    int bh = blockIdx.y;
    int b = bh / H_, h = bh % H_;
    int q0 = blockIdx.x * 128;
    int tid = threadIdx.x, warp = tid >> 5, lane = tid & 31;
    int g = lane >> 2, tig = lane & 3;
    const float* base = qkv + (size_t)b * N_ * (3*C_) + h * D_;
    uint32_t sb = smem_u32(sf);

    for (int idx = tid; idx < 128*16; idx += 256) {
        int r = idx >> 4, c4 = idx & 15;
        int qr = q0 + r;
        float4 f = make_float4(0.f,0.f,0.f,0.f);
        if (qr < N_) f = *(const float4*)(base + (size_t)qr*(3*C_) + c4*4);
        float* dst = Qs + r*68 + c4*4;
        dst[0]=rndtf32(f.x); dst[1]=rndtf32(f.y); dst[2]=rndtf32(f.z); dst[3]=rndtf32(f.w);
    }

#define FA_ISSUE(kt_, buf_) do {                                              \
        uint32_t kb8 = sb + (uint32_t)(8704 + (buf_)*4352)*4u;                \
        uint32_t vb8 = sb + (uint32_t)(17408 + (buf_)*4608)*4u;               \
        _Pragma("unroll")                                                     \
        for (int it = 0; it < 4; it++) {                                      \
            int chunk = tid + it*256;                                         \
            int r = chunk >> 4, c4 = chunk & 15;                              \
            int kr = (kt_)*64 + r;                                            \
            int ok = (kr < N_);                                               \
            const float* ksrc = base + (size_t)(ok ? kr : 0)*(3*C_) + C_   + c4*4; \
            const float* vsrc = base + (size_t)(ok ? kr : 0)*(3*C_) + 2*C_ + c4*4; \
            cp16(kb8 + (uint32_t)(r*68 + c4*4)*4u, ksrc, ok ? 16 : 0);        \
            cp16(vb8 + (uint32_t)(r*72 + c4*4)*4u, vsrc, ok ? 16 : 0);        \
        }                                                                     \
        CP_COMMIT();                                                          \
    } while (0)

    FA_ISSUE(0, 0);
    FA_ISSUE(1, 1);

    float o[8][4];
#pragma unroll
    for (int i = 0; i < 8; i++) { o[i][0]=0.f; o[i][1]=0.f; o[i][2]=0.f; o[i][3]=0.f; }
    float mr0 = -INFINITY, mr1 = -INFINITY, l0 = 0.f, l1 = 0.f;

    float* Pw = Ps + warp*16*68;
    const float* Qw = Qs + warp*16*68;

    for (int kt = 0; kt < 8; kt++) {
        int buf = kt & 1;
        if (kt == 7) { CP_WAIT0(); } else { CP_WAIT1(); }
        __syncthreads();
        const float* Kt = KsB + buf*4352;
        const float* Vt = VsB + buf*4608;

        float s[8][4];
#pragma unroll
        for (int i = 0; i < 8; i++) { s[i][0]=0.f; s[i][1]=0.f; s[i][2]=0.f; s[i][3]=0.f; }
#pragma unroll
        for (int ks = 0; ks < 8; ks++) {
            int k0 = ks*8;
            uint32_t a0 = __float_as_uint(Qw[g*68     + k0 + tig]);
            uint32_t a1 = __float_as_uint(Qw[(g+8)*68 + k0 + tig]);
            uint32_t a2 = __float_as_uint(Qw[g*68     + k0 + tig + 4]);
            uint32_t a3 = __float_as_uint(Qw[(g+8)*68 + k0 + tig + 4]);
#pragma unroll
            for (int ni = 0; ni < 8; ni++) {
                uint32_t b0 = __float_as_uint(Kt[(ni*8+g)*68 + k0 + tig]);
                uint32_t b1 = __float_as_uint(Kt[(ni*8+g)*68 + k0 + tig + 4]);
                mma_tf32(s[ni][0], s[ni][1], s[ni][2], s[ni][3], a0,a1,a2,a3, b0,b1);
            }
        }
        float mc0 = -INFINITY, mc1 = -INFINITY;
#pragma unroll
        for (int ni = 0; ni < 8; ni++) {
            int colb = kt*64 + ni*8 + 2*tig;
#pragma unroll
            for (int cc = 0; cc < 4; cc++) {
                float v = s[ni][cc] * 0.125f;
                if (colb + (cc & 1) >= N_) v = -INFINITY;
                s[ni][cc] = v;
                if (cc < 2) mc0 = fmaxf(mc0, v); else mc1 = fmaxf(mc1, v);
            }
        }
        mc0 = fmaxf(mc0, __shfl_xor_sync(~0u, mc0, 1));
        mc0 = fmaxf(mc0, __shfl_xor_sync(~0u, mc0, 2));
        mc1 = fmaxf(mc1, __shfl_xor_sync(~0u, mc1, 1));
        mc1 = fmaxf(mc1, __shfl_xor_sync(~0u, mc1, 2));
        float mn0 = fmaxf(mr0, mc0), mn1 = fmaxf(mr1, mc1);
        float al0 = expf(mr0 - mn0), al1 = expf(mr1 - mn1);
        mr0 = mn0; mr1 = mn1;
        float ls0 = 0.f, ls1 = 0.f;
#pragma unroll
        for (int ni = 0; ni < 8; ni++) {
            float p0 = expf(s[ni][0] - mn0);
            float p1 = expf(s[ni][1] - mn0);
            float p2 = expf(s[ni][2] - mn1);
            float p3 = expf(s[ni][3] - mn1);
            s[ni][0]=p0; s[ni][1]=p1; s[ni][2]=p2; s[ni][3]=p3;
            ls0 += p0 + p1; ls1 += p2 + p3;
        }
        ls0 += __shfl_xor_sync(~0u, ls0, 1); ls0 += __shfl_xor_sync(~0u, ls0, 2);
        ls1 += __shfl_xor_sync(~0u, ls1, 1); ls1 += __shfl_xor_sync(~0u, ls1, 2);
        l0 = l0*al0 + ls0; l1 = l1*al1 + ls1;

        __syncwarp();
#pragma unroll
        for (int ni = 0; ni < 8; ni++) {
            *(float2*)(Pw + g*68     + ni*8 + 2*tig) = make_float2(rndtf32(s[ni][0]), rndtf32(s[ni][1]));
            *(float2*)(Pw + (g+8)*68 + ni*8 + 2*tig) = make_float2(rndtf32(s[ni][2]), rndtf32(s[ni][3]));
        }
#pragma unroll
        for (int ni = 0; ni < 8; ni++) {
            o[ni][0]*=al0; o[ni][1]*=al0; o[ni][2]*=al1; o[ni][3]*=al1;
        }
        __syncwarp();
#pragma unroll
        for (int ks = 0; ks < 8; ks++) {
            int k0 = ks*8;
            uint32_t a0 = __float_as_uint(Pw[g*68     + k0 + tig]);
            uint32_t a1 = __float_as_uint(Pw[(g+8)*68 + k0 + tig]);
            uint32_t a2 = __float_as_uint(Pw[g*68     + k0 + tig + 4]);
            uint32_t a3 = __float_as_uint(Pw[(g+8)*68 + k0 + tig + 4]);
#pragma unroll
            for (int ni = 0; ni < 8; ni++) {
                uint32_t b0 = __float_as_uint(Vt[(k0+tig)*72   + ni*8 + g]);
                uint32_t b1 = __float_as_uint(Vt[(k0+tig+4)*72 + ni*8 + g]);
                mma_tf32(o[ni][0], o[ni][1], o[ni][2], o[ni][3], a0,a1,a2,a3, b0,b1);
            }
        }
        __syncthreads();
        if (kt + 2 < 8) FA_ISSUE(kt + 2, buf);
    }
#undef FA_ISSUE

    int r0 = q0 + warp*16 + g, r1 = r0 + 8;
    float inv0 = 1.f / l0, inv1 = 1.f / l1;
#pragma unroll
    for (int ni = 0; ni < 8; ni++) {
        int col = h*D_ + ni*8 + 2*tig;
        if (r0 < N_)
            *(float2*)(obuf + ((size_t)b*N_ + r0)*C_ + col) =
                make_float2(rndtf32(o[ni][0]*inv0), rndtf32(o[ni][1]*inv0));
        if (r1 < N_)
            *(float2*)(obuf + ((size_t)b*N_ + r1)*C_ + col) =
                make_float2(rndtf32(o[ni][2]*inv1), rndtf32(o[ni][3]*inv1));
    }
}

// ---------------- cls attention row (exact fp32 softmax of q-row 0) ----------------
__global__ __launch_bounds__(256)
void cls_kernel(const float* __restrict__ qkv, float* __restrict__ cls_acc) {
    __shared__ float q0s[64];
    __shared__ float red[8];
    int bh = blockIdx.x;
    int b = bh / H_, h = bh % H_;
    const float* base = qkv + (size_t)b * N_ * (3*C_) + h * D_;
    int tid = threadIdx.x, lane = tid & 31, warp = tid >> 5;
    if (tid < 64) q0s[tid] = base[tid];
    __syncthreads();

    float s0 = -INFINITY, s1 = -INFINITY;
    {
        int j = tid;
        if (j < N_) {
            float a = 0.f;
            const float* k = base + (size_t)j*(3*C_) + C_;
#pragma unroll 16
            for (int d = 0; d < 64; d++) a += q0s[d]*k[d];
            s0 = a * 0.125f;
        }
        j = tid + 256;
        if (j < N_) {
            float a = 0.f;
            const float* k = base + (size_t)j*(3*C_) + C_;
#pragma unroll 16
            for (int d = 0; d < 64; d++) a += q0s[d]*k[d];
            s1 = a * 0.125f;
        }
    }
    float m = fmaxf(s0, s1);
#pragma unroll
    for (int off = 16; off; off >>= 1) m = fmaxf(m, __shfl_xor_sync(~0u, m, off));
    if (lane == 0) red[warp] = m;
    __syncthreads();
    float M = red[0];
#pragma unroll
    for (int i = 1; i < 8; i++) M = fmaxf(M, red[i]);
    __syncthreads();
    float e0 = expf(s0 - M), e1 = expf(s1 - M);
    float t = e0 + e1;
#pragma unroll
    for (int off = 16; off; off >>= 1) t += __shfl_xor_sync(~0u, t, off);
    if (lane == 0) red[warp] = t;
    __syncthreads();
    float L = 0.f;
#pragma unroll
    for (int i = 0; i < 8; i++) L += red[i];
    float invL = 1.f / (L * (float)H_);
    int j = tid;
    if (j >= 1 && j < N_) atomicAdd(&cls_acc[b*(N_-1) + j - 1], e0 * invL);
    j = tid + 256;
    if (j < N_) atomicAdd(&cls_acc[b*(N_-1) + j - 1], e1 * invL);
}

// ---------------- glb EMA ----------------
__global__ void glb_kernel() {
    int i = blockIdx.x*blockDim.x + threadIdx.x;
    if (i < B_*(N_-1)) {
        g_glb[i] = 0.5f * g_glb[i] + 0.5f * g_cls[i];
        g_cls[i] = 0.f;
    }
}

// ---------------- output ----------------
__global__ void copy_out_kernel(float* __restrict__ out, int out_size) {
    const int NX = B_*N_*C_;
    const int NG = B_*(N_-1);
    for (int i = blockIdx.x*blockDim.x + threadIdx.x; i < out_size;
         i += gridDim.x*blockDim.x) {
        float v = 0.f;
        if (i < NX)            v = g_x[i];
        else if (i < NX + NG)  v = g_glb[i - NX];
        out[i] = v;
    }
}

// ---------------- launch ----------------
extern "C" void kernel_launch(void* const* d_in, const int* in_sizes, int n_in,
                              void* d_out, int out_size) {
    const float* x       = (const float*)d_in[0];
    const float* gattn   = (const float*)d_in[1];
    const float* split_w = (const float*)d_in[2];
    const float* split_b = (const float*)d_in[3];
    const float* ln1_g   = (const float*)d_in[4];
    const float* ln1_b   = (const float*)d_in[5];
    const float* qkv_w   = (const float*)d_in[6];
    const float* qkv_b   = (const float*)d_in[7];
    const float* proj_w  = (const float*)d_in[8];
    const float* proj_b  = (const float*)d_in[9];
    const float* ln2_g   = (const float*)d_in[10];
    const float* ln2_b   = (const float*)d_in[11];
    const float* fc1_w   = (const float*)d_in[12];
    const float* fc1_b   = (const float*)d_in[13];
    const float* fc2_w   = (const float*)d_in[14];
    const float* fc2_b   = (const float*)d_in[15];

    float *px, *ph, *pqkv, *po, *pmlp, *ptok, *pcls;
    float *pwsplit, *pwqkv, *pwproj, *pwfc1, *pwfc2;
    cudaGetSymbolAddress((void**)&px,   g_x);
    cudaGetSymbolAddress((void**)&ph,   g_h);
    cudaGetSymbolAddress((void**)&pqkv, g_qkv);
    cudaGetSymbolAddress((void**)&po,   g_o);
    cudaGetSymbolAddress((void**)&pmlp, g_mlp);
    cudaGetSymbolAddress((void**)&ptok, g_tok);
    cudaGetSymbolAddress((void**)&pcls, g_cls);
    cudaGetSymbolAddress((void**)&pwsplit, g_wsplit);
    cudaGetSymbolAddress((void**)&pwqkv,   g_wqkv);
    cudaGetSymbolAddress((void**)&pwproj,  g_wproj);
    cudaGetSymbolAddress((void**)&pwfc1,   g_wfc1);
    cudaGetSymbolAddress((void**)&pwfc2,   g_wfc2);

    cudaFuncSetAttribute(gemm_cp,    cudaFuncAttributeMaxDynamicSharedMemorySize, GEMM_SMEM);
    cudaFuncSetAttribute(flash_attn, cudaFuncAttributeMaxDynamicSharedMemorySize, FA_SMEM);

    wconv_kernel<<<2048, 256>>>(split_w, pwsplit, SW_SZ);
    wconv_kernel<<<2048, 256>>>(qkv_w,   pwqkv,   L_*QW_SZ);
    wconv_kernel<<<2048, 256>>>(proj_w,  pwproj,  L_*PW_SZ);
    wconv_kernel<<<2048, 256>>>(fc1_w,   pwfc1,   L_*F1_SZ);
    wconv_kernel<<<2048, 256>>>(fc2_w,   pwfc2,   L_*F2_SZ);

    sort_kernel<<<B_, 256>>>(gattn);
    gather_kernel<<<B_*197, 256>>>(x);
    init_kernel<<<(B_*(N_-1) + 255)/256, 256>>>();

    {
        int M = B_*SPLN, N = 4*C_, K = C_;
        dim3 grid(N/128, (M + BM - 1)/BM);
        gemm_cp<<<grid, 256, GEMM_SMEM>>>(ptok, pwsplit, split_b, nullptr, px, M, N, K, 3);
    }

    for (int l = 0; l < L_; l++) {
        const float* l1g = ln1_g + l*C_;
        const float* l1b = ln1_b + l*C_;
        const float* qw  = pwqkv + (size_t)l*QW_SZ;
        const float* qb  = qkv_b + l*3*C_;
        const float* pw  = pwproj + (size_t)l*PW_SZ;
        const float* pb  = proj_b + l*C_;
        const float* l2g = ln2_g + l*C_;
        const float* l2b = ln2_b + l*C_;
        const float* w1  = pwfc1 + (size_t)l*F1_SZ;
        const float* b1  = fc1_b + l*HM_;
        const float* w2  = pwfc2 + (size_t)l*F2_SZ;
        const float* b2  = fc2_b + l*C_;

        ln_kernel<<<M_ROWS, 256>>>(px, ph, l1g, l1b);

        { dim3 grid((3*C_)/128, (M_ROWS + BM - 1)/BM);
          gemm_cp<<<grid, 256, GEMM_SMEM>>>(ph, qw, qb, nullptr, pqkv, M_ROWS, 3*C_, C_, 0); }

        cls_kernel<<<B_*H_, 256>>>(pqkv, pcls);

        { dim3 grid(4, B_*H_);
          flash_attn<<<grid, 256, FA_SMEM>>>(pqkv, po); }

        glb_kernel<<<(B_*(N_-1) + 255)/256, 256>>>();

        { dim3 grid(C_/128, (M_ROWS + BM - 1)/BM);
          gemm_cp<<<grid, 256, GEMM_SMEM>>>(po, pw, pb, px, px, M_ROWS, C_, C_, 2); }

        ln_kernel<<<M_ROWS, 256>>>(px, ph, l2g, l2b);

        { dim3 grid(HM_/128, (M_ROWS + BM - 1)/BM);
          gemm_cp<<<grid, 256, GEMM_SMEM>>>(ph, w1, b1, nullptr, pmlp, M_ROWS, HM_, C_, 1); }

        { dim3 grid(C_/128, (M_ROWS + BM - 1)/BM);
          gemm_cp<<<grid, 256, GEMM_SMEM>>>(pmlp, w2, b2, px, px, M_ROWS, C_, HM_, 2); }
    }

    copy_out_kernel<<<2048, 256>>>((float*)d_out, out_size);
}

// round 7
// speedup vs baseline: 1.4724x; 1.4724x over previous
#include <cuda_runtime.h>
#include <cuda_fp16.h>
#include <math.h>
#include <stdint.h>

// ---------------- problem constants ----------------
#define B_    16
#define NTOK  196
#define SPLN  98
#define N_    491          // 1 + 98*4 + 98
#define C_    768
#define HM_   3072
#define H_    12
#define D_    64
#define L_    4
#define M_ROWS (B_*N_)     // 7856

// weight sizes
#define SW_SZ   (C_*4*C_)
#define QW_SZ   (C_*3*C_)
#define PW_SZ   (C_*C_)
#define F1_SZ   (C_*HM_)
#define F2_SZ   (HM_*C_)

// ---------------- device scratch ----------------
__device__ float  g_x   [B_*N_*C_];          // residual stream (fp32)
__device__ __half g_h   [B_*N_*C_];          // LN output (fp16, GEMM input)
__device__ float  g_qkv [B_*N_*3*C_];        // qkv (fp32, attention input)
__device__ __half g_o   [B_*N_*C_];          // attention output (fp16, GEMM input)
__device__ __half g_mlp [B_*N_*HM_];         // fc1 output (fp16, GEMM input)
__device__ __half g_tok [B_*SPLN*C_];        // gathered top tokens (fp16)
__device__ int    g_ord [B_*NTOK];
__device__ float  g_glb [B_*(N_-1)];
__device__ float  g_cls [B_*(N_-1)];
// fp16 weights
__device__ __half g_wsplit[SW_SZ];
__device__ __half g_wqkv  [L_*QW_SZ];
__device__ __half g_wproj [L_*PW_SZ];
__device__ __half g_wfc1  [L_*F1_SZ];
__device__ __half g_wfc2  [L_*F2_SZ];

// ---------------- helpers ----------------
__device__ __forceinline__ uint32_t smem_u32(const void* p) {
    uint32_t a;
    asm("{ .reg .u64 t; cvta.to.shared.u64 t, %1; cvt.u32.u64 %0, t; }" : "=r"(a) : "l"(p));
    return a;
}
__device__ __forceinline__ uint32_t f2tf32(float x) {
    uint32_t r;
    asm("cvt.rna.tf32.f32 %0, %1;" : "=r"(r) : "f"(x));
    return r;
}
__device__ __forceinline__ float rndtf32(float x) { return __uint_as_float(f2tf32(x)); }

__device__ __forceinline__ void mma_tf32(float& c0, float& c1, float& c2, float& c3,
                                         uint32_t a0, uint32_t a1, uint32_t a2, uint32_t a3,
                                         uint32_t b0, uint32_t b1) {
    asm volatile("mma.sync.aligned.m16n8k8.row.col.f32.tf32.tf32.f32 "
                 "{%0,%1,%2,%3}, {%4,%5,%6,%7}, {%8,%9}, {%0,%1,%2,%3};"
                 : "+f"(c0), "+f"(c1), "+f"(c2), "+f"(c3)
                 : "r"(a0), "r"(a1), "r"(a2), "r"(a3), "r"(b0), "r"(b1));
}
__device__ __forceinline__ void mma_f16(float& c0, float& c1, float& c2, float& c3,
                                        uint32_t a0, uint32_t a1, uint32_t a2, uint32_t a3,
                                        uint32_t b0, uint32_t b1) {
    asm volatile("mma.sync.aligned.m16n8k16.row.col.f32.f16.f16.f32 "
                 "{%0,%1,%2,%3}, {%4,%5,%6,%7}, {%8,%9}, {%0,%1,%2,%3};"
                 : "+f"(c0), "+f"(c1), "+f"(c2), "+f"(c3)
                 : "r"(a0), "r"(a1), "r"(a2), "r"(a3), "r"(b0), "r"(b1));
}
__device__ __forceinline__ void ldsm_x4(uint32_t& r0, uint32_t& r1, uint32_t& r2, uint32_t& r3,
                                        uint32_t addr) {
    asm volatile("ldmatrix.sync.aligned.m8n8.x4.shared.b16 {%0,%1,%2,%3}, [%4];"
                 : "=r"(r0), "=r"(r1), "=r"(r2), "=r"(r3) : "r"(addr));
}
__device__ __forceinline__ void ldsm_x4_t(uint32_t& r0, uint32_t& r1, uint32_t& r2, uint32_t& r3,
                                          uint32_t addr) {
    asm volatile("ldmatrix.sync.aligned.m8n8.x4.trans.shared.b16 {%0,%1,%2,%3}, [%4];"
                 : "=r"(r0), "=r"(r1), "=r"(r2), "=r"(r3) : "r"(addr));
}
__device__ __forceinline__ void cp16(uint32_t dst, const void* src, int sz) {
    asm volatile("cp.async.cg.shared.global [%0], [%1], 16, %2;"
                 :: "r"(dst), "l"(src), "r"(sz) : "memory");
}
#define CP_COMMIT() asm volatile("cp.async.commit_group;" ::: "memory")
#define CP_WAIT1()  asm volatile("cp.async.wait_group 1;" ::: "memory")
#define CP_WAIT0()  asm volatile("cp.async.wait_group 0;" ::: "memory")

// ---------------- weight convert fp32 -> fp16 ----------------
__global__ void wconv_kernel(const float* __restrict__ src, __half* __restrict__ dst, int n) {
    int stride = gridDim.x * blockDim.x;
    for (int i = blockIdx.x*blockDim.x + threadIdx.x; i < n; i += stride)
        dst[i] = __float2half_rn(src[i]);
}

// ---------------- sort ----------------
__global__ void sort_kernel(const float* __restrict__ attn) {
    __shared__ float sv[256];
    __shared__ int   si[256];
    int b = blockIdx.x, t = threadIdx.x;
    sv[t] = (t < NTOK) ? attn[b*NTOK + t] : -INFINITY;
    si[t] = t;
    __syncthreads();
    for (int k = 2; k <= 256; k <<= 1) {
        for (int j = k >> 1; j > 0; j >>= 1) {
            int ix = t ^ j;
            if (ix > t) {
                float v1 = sv[t], v2 = sv[ix];
                int   i1 = si[t], i2 = si[ix];
                bool before = (v1 > v2) || (v1 == v2 && i1 < i2);
                bool doswap = ((t & k) == 0) ? (!before) : before;
                if (doswap) { sv[t]=v2; sv[ix]=v1; si[t]=i2; si[ix]=i1; }
            }
            __syncthreads();
        }
    }
    if (t < NTOK) g_ord[b*NTOK + t] = si[t];
}

// ---------------- gather ----------------
__global__ void gather_kernel(const float* __restrict__ xin) {
    int blk = blockIdx.x;
    int b = blk / 197, r = blk % 197;
    int t = threadIdx.x;
    if (r == 0) {
        const float* srow = xin + (size_t)b*197*C_;
        float* drow = g_x + (size_t)b*N_*C_;
        drow[t] = srow[t]; drow[t+256] = srow[t+256]; drow[t+512] = srow[t+512];
    } else if (r <= SPLN) {
        int i = r - 1;
        int ord = g_ord[b*NTOK + i];
        const float* srow = xin + ((size_t)b*197 + 1 + ord)*C_;
        __half* drow = g_tok + ((size_t)b*SPLN + i)*C_;
        drow[t]     = __float2half_rn(srow[t]);
        drow[t+256] = __float2half_rn(srow[t+256]);
        drow[t+512] = __float2half_rn(srow[t+512]);
    } else {
        int i = r - 1 - SPLN;
        int ord = g_ord[b*NTOK + SPLN + i];
        const float* srow = xin + ((size_t)b*197 + 1 + ord)*C_;
        float* drow = g_x + ((size_t)b*N_ + 1 + SPLN*4 + i)*C_;
        drow[t] = srow[t]; drow[t+256] = srow[t+256]; drow[t+512] = srow[t+512];
    }
}

__global__ void init_kernel() {
    int i = blockIdx.x*blockDim.x + threadIdx.x;
    if (i < B_*(N_-1)) { g_glb[i] = 0.f; g_cls[i] = 0.f; }
}

// ---------------- fp16 tensor-core GEMM: 128x128 tile, BK=32, warp 64x32, 3-stage cp.async ----
// A: half [M][K], W: half [K][N], bias/resid fp32.
// modes: 0 bias->f32 | 1 bias+gelu->HALF | 2 bias+residual->f32 | 3 bias+split-remap->f32
#define A_ST 40              // halves per A row (32 + 8 pad) -> 80 bytes
#define W_ST 136             // halves per W row (128 + 8 pad) -> 272 bytes
#define A_BY (128*A_ST*2)    // 10240 bytes
#define W_BY (32*W_ST*2)     // 8704 bytes
#define BUF_BY (A_BY + W_BY) // 18944 bytes
#define NSTAGE 3
#define GEMM_SMEM (NSTAGE*BUF_BY)   // 56832 bytes

__global__ __launch_bounds__(256, 2)
void gemm_h(const __half* __restrict__ A, const __half* __restrict__ W,
            const float* __restrict__ bias, const float* __restrict__ resid,
            void* __restrict__ out, int M, int N, int K, int mode) {
    extern __shared__ char smc[];
    int tid  = threadIdx.x;
    int m0   = blockIdx.y * 128, n0 = blockIdx.x * 128;
    int warp = tid >> 5, lane = tid & 31;
    int g    = lane >> 2, tig = lane & 3;
    int wm0  = (warp >> 2) * 64;      // 2 warps in M
    int wn0  = (warp & 3) * 32;       // 4 warps in N

    uint32_t sbase = smem_u32(smc);

    float acc[4][4][4];
#pragma unroll
    for (int i = 0; i < 4; i++)
#pragma unroll
        for (int j = 0; j < 4; j++)
#pragma unroll
            for (int c = 0; c < 4; c++) acc[i][j][c] = 0.f;

    int nt = K >> 5;

#define ISSUE_TILE(kc_, buf_) do {                                              \
        uint32_t ab = sbase + (uint32_t)(buf_) * BUF_BY;                        \
        uint32_t wb = ab + A_BY;                                               \
        {   /* A: 128 rows x 32 halves; thread: row=tid>>1, c=tid&1 (32B) */    \
            int row = tid >> 1, c = tid & 1;                                    \
            int gr = m0 + row;                                                  \
            int ok = (gr < M);                                                  \
            const __half* src = A + (size_t)(ok ? gr : 0)*K + (kc_)*32 + c*16;  \
            uint32_t d = ab + (uint32_t)row*(A_ST*2) + (uint32_t)c*32;          \
            cp16(d,      src,     ok ? 16 : 0);                                 \
            cp16(d + 16, src + 8, ok ? 16 : 0);                                 \
        }                                                                       \
        {   /* W: 32 rows x 128 halves; thread: row=tid>>3, seg=tid&7 (32B) */  \
            int kr = tid >> 3, seg = tid & 7;                                   \
            const __half* src = W + (size_t)((kc_)*32 + kr)*N + n0 + seg*16;    \
            uint32_t d = wb + (uint32_t)kr*(W_ST*2) + (uint32_t)seg*32;         \
            cp16(d,      src,     16);                                          \
            cp16(d + 16, src + 8, 16);                                          \
        }                                                                       \
        CP_COMMIT();                                                            \
    } while (0)

    ISSUE_TILE(0, 0);
    if (nt > 1) ISSUE_TILE(1, 1);

    // per-lane ldmatrix address components (element offsets)
    int a_row = lane & 15;            // m within 16
    int a_col = (lane >> 4) << 3;     // 0 or 8 (k)
    int b_krw = (lane & 7) + (((lane >> 4) & 1) << 3);   // k within 16
    int b_ncl = ((lane >> 3) & 1) << 3;                  // 0 or 8 (n)

    for (int kc = 0; kc < nt; kc++) {
        int buf = kc % NSTAGE;
        if (kc == nt - 1) { CP_WAIT0(); } else { CP_WAIT1(); }
        __syncthreads();
        if (kc + 2 < nt) ISSUE_TILE(kc + 2, (kc + 2) % NSTAGE);

        uint32_t ab = sbase + (uint32_t)buf * BUF_BY;
        uint32_t wb = ab + A_BY;
#pragma unroll
        for (int ks = 0; ks < 2; ks++) {
            int k0 = ks * 16;
            uint32_t a[4][4], b[4][2];
#pragma unroll
            for (int mi = 0; mi < 4; mi++) {
                uint32_t addr = ab + (uint32_t)((wm0 + mi*16 + a_row)*A_ST + k0 + a_col)*2;
                ldsm_x4(a[mi][0], a[mi][1], a[mi][2], a[mi][3], addr);
            }
#pragma unroll
            for (int np = 0; np < 2; np++) {
                uint32_t addr = wb + (uint32_t)((k0 + b_krw)*W_ST + wn0 + np*16 + b_ncl)*2;
                uint32_t r0, r1, r2, r3;
                ldsm_x4_t(r0, r1, r2, r3, addr);
                b[np*2][0]   = r0; b[np*2][1]   = r2;
                b[np*2+1][0] = r1; b[np*2+1][1] = r3;
            }
#pragma unroll
            for (int mi = 0; mi < 4; mi++)
#pragma unroll
                for (int ni = 0; ni < 4; ni++)
                    mma_f16(acc[mi][ni][0], acc[mi][ni][1], acc[mi][ni][2], acc[mi][ni][3],
                            a[mi][0], a[mi][1], a[mi][2], a[mi][3],
                            b[ni][0], b[ni][1]);
        }
    }
#undef ISSUE_TILE

    // epilogue
#pragma unroll
    for (int mi = 0; mi < 4; mi++) {
#pragma unroll
        for (int half_ = 0; half_ < 2; half_++) {
            int row = m0 + wm0 + mi*16 + g + half_*8;
            if (row >= M) continue;
#pragma unroll
            for (int ni = 0; ni < 4; ni++) {
                int col = n0 + wn0 + ni*8 + tig*2;
                float v0 = acc[mi][ni][half_*2]     + bias[col];
                float v1 = acc[mi][ni][half_*2 + 1] + bias[col+1];
                if (mode == 1) {
                    v0 = 0.5f*v0*(1.0f + erff(v0*0.70710678118654752f));
                    v1 = 0.5f*v1*(1.0f + erff(v1*0.70710678118654752f));
                    *(__half2*)((__half*)out + (size_t)row*N + col) =
                        __floats2half2_rn(v0, v1);
                } else if (mode == 2) {
                    const float* rrow = resid + (size_t)row*N;
                    v0 += rrow[col];
                    v1 += rrow[col+1];
                    *(float2*)((float*)out + (size_t)row*N + col) = make_float2(v0, v1);
                } else if (mode == 3) {
                    int bb = row / SPLN, s = row % SPLN;
                    float* orow = (float*)out + ((size_t)bb*N_ + 1 + (size_t)s*4)*C_;
                    *(float2*)(orow + col) = make_float2(v0, v1);
                } else {
                    *(float2*)((float*)out + (size_t)row*N + col) = make_float2(v0, v1);
                }
            }
        }
    }
}

// ---------------- layernorm (fp16 output) ----------------
__global__ __launch_bounds__(256)
void ln_kernel(const float* __restrict__ in, __half* __restrict__ out,
               const float* __restrict__ gamma, const float* __restrict__ beta) {
    int row = blockIdx.x, t = threadIdx.x;
    const float* xr = in + (size_t)row * C_;
    float v0 = xr[t], v1 = xr[t+256], v2 = xr[t+512];
    __shared__ float red[8];
    float s = v0 + v1 + v2;
#pragma unroll
    for (int o = 16; o; o >>= 1) s += __shfl_xor_sync(~0u, s, o);
    if ((t & 31) == 0) red[t >> 5] = s;
    __syncthreads();
    float tot = 0.f;
#pragma unroll
    for (int i = 0; i < 8; i++) tot += red[i];
    float mean = tot * (1.0f / C_);
    __syncthreads();
    float d0 = v0 - mean, d1 = v1 - mean, d2 = v2 - mean;
    float s2 = d0*d0 + d1*d1 + d2*d2;
#pragma unroll
    for (int o = 16; o; o >>= 1) s2 += __shfl_xor_sync(~0u, s2, o);
    if ((t & 31) == 0) red[t >> 5] = s2;
    __syncthreads();
    float tot2 = 0.f;
#pragma unroll
    for (int i = 0; i < 8; i++) tot2 += red[i];
    float inv = rsqrtf(tot2 * (1.0f / C_) + 1e-6f);
    __half* orow = out + (size_t)row * C_;
    orow[t]       = __float2half_rn(d0 * inv * gamma[t]       + beta[t]);
    orow[t + 256] = __float2half_rn(d1 * inv * gamma[t + 256] + beta[t + 256]);
    orow[t + 512] = __float2half_rn(d2 * inv * gamma[t + 512] + beta[t + 512]);
}

// ---------------- flash attention (tf32 mma), 128 q-rows per CTA, fp16 output ------
#define FA_SMEM 141312
__global__ __launch_bounds__(256)
void flash_attn(const float* __restrict__ qkv, __half* __restrict__ obuf) {
    extern __shared__ float sf[];
    float* Qs  = sf;
    float* KsB = sf + 8704;
    float* VsB = sf + 17408;
    float* Ps  = sf + 26624;

    int bh = blockIdx.y;
    int b = bh / H_, h = bh % H_;
    int q0 = blockIdx.x * 128;
    int tid = threadIdx.x, warp = tid >> 5, lane = tid & 31;
    int g = lane >> 2, tig = lane & 3;
    const float* base = qkv + (size_t)b * N_ * (3*C_) + h * D_;
    uint32_t sb = smem_u32(sf);

    for (int idx = tid; idx < 128*16; idx += 256) {
        int r = idx >> 4, c4 = idx & 15;
        int qr = q0 + r;
        float4 f = make_float4(0.f,0.f,0.f,0.f);
        if (qr < N_) f = *(const float4*)(base + (size_t)qr*(3*C_) + c4*4);
        float* dst = Qs + r*68 + c4*4;
        dst[0]=rndtf32(f.x); dst[1]=rndtf32(f.y); dst[2]=rndtf32(f.z); dst[3]=rndtf32(f.w);
    }

#define FA_ISSUE(kt_, buf_) do {                                              \
        uint32_t kb8 = sb + (uint32_t)(8704 + (buf_)*4352)*4u;                \
        uint32_t vb8 = sb + (uint32_t)(17408 + (buf_)*4608)*4u;               \
        _Pragma("unroll")                                                     \
        for (int it = 0; it < 4; it++) {                                      \
            int chunk = tid + it*256;                                         \
            int r = chunk >> 4, c4 = chunk & 15;                              \
            int kr = (kt_)*64 + r;                                            \
            int ok = (kr < N_);                                               \
            const float* ksrc = base + (size_t)(ok ? kr : 0)*(3*C_) + C_   + c4*4; \
            const float* vsrc = base + (size_t)(ok ? kr : 0)*(3*C_) + 2*C_ + c4*4; \
            cp16(kb8 + (uint32_t)(r*68 + c4*4)*4u, ksrc, ok ? 16 : 0);        \
            cp16(vb8 + (uint32_t)(r*72 + c4*4)*4u, vsrc, ok ? 16 : 0);        \
        }                                                                     \
        CP_COMMIT();                                                          \
    } while (0)

    FA_ISSUE(0, 0);
    FA_ISSUE(1, 1);

    float o[8][4];
#pragma unroll
    for (int i = 0; i < 8; i++) { o[i][0]=0.f; o[i][1]=0.f; o[i][2]=0.f; o[i][3]=0.f; }
    float mr0 = -INFINITY, mr1 = -INFINITY, l0 = 0.f, l1 = 0.f;

    float* Pw = Ps + warp*16*68;
    const float* Qw = Qs + warp*16*68;

    for (int kt = 0; kt < 8; kt++) {
        int buf = kt & 1;
        if (kt == 7) { CP_WAIT0(); } else { CP_WAIT1(); }
        __syncthreads();
        const float* Kt = KsB + buf*4352;
        const float* Vt = VsB + buf*4608;

        float s[8][4];
#pragma unroll
        for (int i = 0; i < 8; i++) { s[i][0]=0.f; s[i][1]=0.f; s[i][2]=0.f; s[i][3]=0.f; }
#pragma unroll
        for (int ks = 0; ks < 8; ks++) {
            int k0 = ks*8;
            uint32_t a0 = __float_as_uint(Qw[g*68     + k0 + tig]);
            uint32_t a1 = __float_as_uint(Qw[(g+8)*68 + k0 + tig]);
            uint32_t a2 = __float_as_uint(Qw[g*68     + k0 + tig + 4]);
            uint32_t a3 = __float_as_uint(Qw[(g+8)*68 + k0 + tig + 4]);
#pragma unroll
            for (int ni = 0; ni < 8; ni++) {
                uint32_t b0 = __float_as_uint(Kt[(ni*8+g)*68 + k0 + tig]);
                uint32_t b1 = __float_as_uint(Kt[(ni*8+g)*68 + k0 + tig + 4]);
                mma_tf32(s[ni][0], s[ni][1], s[ni][2], s[ni][3], a0,a1,a2,a3, b0,b1);
            }
        }
        float mc0 = -INFINITY, mc1 = -INFINITY;
#pragma unroll
        for (int ni = 0; ni < 8; ni++) {
            int colb = kt*64 + ni*8 + 2*tig;
#pragma unroll
            for (int cc = 0; cc < 4; cc++) {
                float v = s[ni][cc] * 0.125f;
                if (colb + (cc & 1) >= N_) v = -INFINITY;
                s[ni][cc] = v;
                if (cc < 2) mc0 = fmaxf(mc0, v); else mc1 = fmaxf(mc1, v);
            }
        }
        mc0 = fmaxf(mc0, __shfl_xor_sync(~0u, mc0, 1));
        mc0 = fmaxf(mc0, __shfl_xor_sync(~0u, mc0, 2));
        mc1 = fmaxf(mc1, __shfl_xor_sync(~0u, mc1, 1));
        mc1 = fmaxf(mc1, __shfl_xor_sync(~0u, mc1, 2));
        float mn0 = fmaxf(mr0, mc0), mn1 = fmaxf(mr1, mc1);
        float al0 = expf(mr0 - mn0), al1 = expf(mr1 - mn1);
        mr0 = mn0; mr1 = mn1;
        float ls0 = 0.f, ls1 = 0.f;
#pragma unroll
        for (int ni = 0; ni < 8; ni++) {
            float p0 = expf(s[ni][0] - mn0);
            float p1 = expf(s[ni][1] - mn0);
            float p2 = expf(s[ni][2] - mn1);
            float p3 = expf(s[ni][3] - mn1);
            s[ni][0]=p0; s[ni][1]=p1; s[ni][2]=p2; s[ni][3]=p3;
            ls0 += p0 + p1; ls1 += p2 + p3;
        }
        ls0 += __shfl_xor_sync(~0u, ls0, 1); ls0 += __shfl_xor_sync(~0u, ls0, 2);
        ls1 += __shfl_xor_sync(~0u, ls1, 1); ls1 += __shfl_xor_sync(~0u, ls1, 2);
        l0 = l0*al0 + ls0; l1 = l1*al1 + ls1;

        __syncwarp();
#pragma unroll
        for (int ni = 0; ni < 8; ni++) {
            *(float2*)(Pw + g*68     + ni*8 + 2*tig) = make_float2(rndtf32(s[ni][0]), rndtf32(s[ni][1]));
            *(float2*)(Pw + (g+8)*68 + ni*8 + 2*tig) = make_float2(rndtf32(s[ni][2]), rndtf32(s[ni][3]));
        }
#pragma unroll
        for (int ni = 0; ni < 8; ni++) {
            o[ni][0]*=al0; o[ni][1]*=al0; o[ni][2]*=al1; o[ni][3]*=al1;
        }
        __syncwarp();
#pragma unroll
        for (int ks = 0; ks < 8; ks++) {
            int k0 = ks*8;
            uint32_t a0 = __float_as_uint(Pw[g*68     + k0 + tig]);
            uint32_t a1 = __float_as_uint(Pw[(g+8)*68 + k0 + tig]);
            uint32_t a2 = __float_as_uint(Pw[g*68     + k0 + tig + 4]);
            uint32_t a3 = __float_as_uint(Pw[(g+8)*68 + k0 + tig + 4]);
#pragma unroll
            for (int ni = 0; ni < 8; ni++) {
                uint32_t b0 = __float_as_uint(Vt[(k0+tig)*72   + ni*8 + g]);
                uint32_t b1 = __float_as_uint(Vt[(k0+tig+4)*72 + ni*8 + g]);
                mma_tf32(o[ni][0], o[ni][1], o[ni][2], o[ni][3], a0,a1,a2,a3, b0,b1);
            }
        }
        __syncthreads();
        if (kt + 2 < 8) FA_ISSUE(kt + 2, buf);
    }
#undef FA_ISSUE

    int r0 = q0 + warp*16 + g, r1 = r0 + 8;
    float inv0 = 1.f / l0, inv1 = 1.f / l1;
#pragma unroll
    for (int ni = 0; ni < 8; ni++) {
        int col = h*D_ + ni*8 + 2*tig;
        if (r0 < N_)
            *(__half2*)(obuf + ((size_t)b*N_ + r0)*C_ + col) =
                __floats2half2_rn(o[ni][0]*inv0, o[ni][1]*inv0);
        if (r1 < N_)
            *(__half2*)(obuf + ((size_t)b*N_ + r1)*C_ + col) =
                __floats2half2_rn(o[ni][2]*inv1, o[ni][3]*inv1);
    }
}

// ---------------- cls attention row (exact fp32 softmax of q-row 0) ----------------
__global__ __launch_bounds__(256)
void cls_kernel(const float* __restrict__ qkv, float* __restrict__ cls_acc) {
    __shared__ float q0s[64];
    __shared__ float red[8];
    int bh = blockIdx.x;
    int b = bh / H_, h = bh % H_;
    const float* base = qkv + (size_t)b * N_ * (3*C_) + h * D_;
    int tid = threadIdx.x, lane = tid & 31, warp = tid >> 5;
    if (tid < 64) q0s[tid] = base[tid];
    __syncthreads();

    float s0 = -INFINITY, s1 = -INFINITY;
    {
        int j = tid;
        if (j < N_) {
            float a = 0.f;
            const float* k = base + (size_t)j*(3*C_) + C_;
#pragma unroll 16
            for (int d = 0; d < 64; d++) a += q0s[d]*k[d];
            s0 = a * 0.125f;
        }
        j = tid + 256;
        if (j < N_) {
            float a = 0.f;
            const float* k = base + (size_t)j*(3*C_) + C_;
#pragma unroll 16
            for (int d = 0; d < 64; d++) a += q0s[d]*k[d];
            s1 = a * 0.125f;
        }
    }
    float m = fmaxf(s0, s1);
#pragma unroll
    for (int off = 16; off; off >>= 1) m = fmaxf(m, __shfl_xor_sync(~0u, m, off));
    if (lane == 0) red[warp] = m;
    __syncthreads();
    float M = red[0];
#pragma unroll
    for (int i = 1; i < 8; i++) M = fmaxf(M, red[i]);
    __syncthreads();
    float e0 = expf(s0 - M), e1 = expf(s1 - M);
    float t = e0 + e1;
#pragma unroll
    for (int off = 16; off; off >>= 1) t += __shfl_xor_sync(~0u, t, off);
    if (lane == 0) red[warp] = t;
    __syncthreads();
    float L = 0.f;
#pragma unroll
    for (int i = 0; i < 8; i++) L += red[i];
    float invL = 1.f / (L * (float)H_);
    int j = tid;
    if (j >= 1 && j < N_) atomicAdd(&cls_acc[b*(N_-1) + j - 1], e0 * invL);
    j = tid + 256;
    if (j < N_) atomicAdd(&cls_acc[b*(N_-1) + j - 1], e1 * invL);
}

// ---------------- glb EMA ----------------
__global__ void glb_kernel() {
    int i = blockIdx.x*blockDim.x + threadIdx.x;
    if (i < B_*(N_-1)) {
        g_glb[i] = 0.5f * g_glb[i] + 0.5f * g_cls[i];
        g_cls[i] = 0.f;
    }
}

// ---------------- output ----------------
__global__ void copy_out_kernel(float* __restrict__ out, int out_size) {
    const int NX = B_*N_*C_;
    const int NG = B_*(N_-1);
    for (int i = blockIdx.x*blockDim.x + threadIdx.x; i < out_size;
         i += gridDim.x*blockDim.x) {
        float v = 0.f;
        if (i < NX)            v = g_x[i];
        else if (i < NX + NG)  v = g_glb[i - NX];
        out[i] = v;
    }
}

// ---------------- launch ----------------
extern "C" void kernel_launch(void* const* d_in, const int* in_sizes, int n_in,
                              void* d_out, int out_size) {
    const float* x       = (const float*)d_in[0];
    const float* gattn   = (const float*)d_in[1];
    const float* split_w = (const float*)d_in[2];
    const float* split_b = (const float*)d_in[3];
    const float* ln1_g   = (const float*)d_in[4];
    const float* ln1_b   = (const float*)d_in[5];
    const float* qkv_w   = (const float*)d_in[6];
    const float* qkv_b   = (const float*)d_in[7];
    const float* proj_w  = (const float*)d_in[8];
    const float* proj_b  = (const float*)d_in[9];
    const float* ln2_g   = (const float*)d_in[10];
    const float* ln2_b   = (const float*)d_in[11];
    const float* fc1_w   = (const float*)d_in[12];
    const float* fc1_b   = (const float*)d_in[13];
    const float* fc2_w   = (const float*)d_in[14];
    const float* fc2_b   = (const float*)d_in[15];

    float *px, *pqkv, *pcls;
    __half *ph, *po, *pmlp, *ptok;
    __half *pwsplit, *pwqkv, *pwproj, *pwfc1, *pwfc2;
    cudaGetSymbolAddress((void**)&px,   g_x);
    cudaGetSymbolAddress((void**)&ph,   g_h);
    cudaGetSymbolAddress((void**)&pqkv, g_qkv);
    cudaGetSymbolAddress((void**)&po,   g_o);
    cudaGetSymbolAddress((void**)&pmlp, g_mlp);
    cudaGetSymbolAddress((void**)&ptok, g_tok);
    cudaGetSymbolAddress((void**)&pcls, g_cls);
    cudaGetSymbolAddress((void**)&pwsplit, g_wsplit);
    cudaGetSymbolAddress((void**)&pwqkv,   g_wqkv);
    cudaGetSymbolAddress((void**)&pwproj,  g_wproj);
    cudaGetSymbolAddress((void**)&pwfc1,   g_wfc1);
    cudaGetSymbolAddress((void**)&pwfc2,   g_wfc2);

    cudaFuncSetAttribute(gemm_h,     cudaFuncAttributeMaxDynamicSharedMemorySize, GEMM_SMEM);
    cudaFuncSetAttribute(flash_attn, cudaFuncAttributeMaxDynamicSharedMemorySize, FA_SMEM);

    wconv_kernel<<<2048, 256>>>(split_w, pwsplit, SW_SZ);
    wconv_kernel<<<2048, 256>>>(qkv_w,   pwqkv,   L_*QW_SZ);
    wconv_kernel<<<2048, 256>>>(proj_w,  pwproj,  L_*PW_SZ);
    wconv_kernel<<<2048, 256>>>(fc1_w,   pwfc1,   L_*F1_SZ);
    wconv_kernel<<<2048, 256>>>(fc2_w,   pwfc2,   L_*F2_SZ);

    sort_kernel<<<B_, 256>>>(gattn);
    gather_kernel<<<B_*197, 256>>>(x);
    init_kernel<<<(B_*(N_-1) + 255)/256, 256>>>();

    {   // split GEMM: M=1568, N=3072, K=768, row-remap into g_x (fp32)
        int M = B_*SPLN, N = 4*C_, K = C_;
        dim3 grid(N/128, (M + 127)/128);
        gemm_h<<<grid, 256, GEMM_SMEM>>>(ptok, pwsplit, split_b, nullptr, px, M, N, K, 3);
    }

    for (int l = 0; l < L_; l++) {
        const float* l1g = ln1_g + l*C_;
        const float* l1b = ln1_b + l*C_;
        const __half* qw = pwqkv + (size_t)l*QW_SZ;
        const float* qb  = qkv_b + l*3*C_;
        const __half* pw = pwproj + (size_t)l*PW_SZ;
        const float* pb  = proj_b + l*C_;
        const float* l2g = ln2_g + l*C_;
        const float* l2b = ln2_b + l*C_;
        const __half* w1 = pwfc1 + (size_t)l*F1_SZ;
        const float* b1  = fc1_b + l*HM_;
        const __half* w2 = pwfc2 + (size_t)l*F2_SZ;
        const float* b2  = fc2_b + l*C_;

        ln_kernel<<<M_ROWS, 256>>>(px, ph, l1g, l1b);

        { dim3 grid((3*C_)/128, (M_ROWS + 127)/128);
          gemm_h<<<grid, 256, GEMM_SMEM>>>(ph, qw, qb, nullptr, pqkv, M_ROWS, 3*C_, C_, 0); }

        cls_kernel<<<B_*H_, 256>>>(pqkv, pcls);

        { dim3 grid(4, B_*H_);
          flash_attn<<<grid, 256, FA_SMEM>>>(pqkv, po); }

        glb_kernel<<<(B_*(N_-1) + 255)/256, 256>>>();

        { dim3 grid(C_/128, (M_ROWS + 127)/128);
          gemm_h<<<grid, 256, GEMM_SMEM>>>(po, pw, pb, px, px, M_ROWS, C_, C_, 2); }

        ln_kernel<<<M_ROWS, 256>>>(px, ph, l2g, l2b);

        { dim3 grid(HM_/128, (M_ROWS + 127)/128);
          gemm_h<<<grid, 256, GEMM_SMEM>>>(ph, w1, b1, nullptr, pmlp, M_ROWS, HM_, C_, 1); }

        { dim3 grid(C_/128, (M_ROWS + 127)/128);
          gemm_h<<<grid, 256, GEMM_SMEM>>>(pmlp, w2, b2, px, px, M_ROWS, C_, HM_, 2); }
    }

    copy_out_kernel<<<2048, 256>>>((float*)d_out, out_size);
}

// round 8
// speedup vs baseline: 1.6497x; 1.1204x over previous
#include <cuda_runtime.h>
#include <cuda_fp16.h>
#include <math.h>
#include <stdint.h>

// ---------------- problem constants ----------------
#define B_    16
#define NTOK  196
#define SPLN  98
#define N_    491          // 1 + 98*4 + 98
#define C_    768
#define HM_   3072
#define H_    12
#define D_    64
#define L_    4
#define M_ROWS (B_*N_)     // 7856

// weight sizes
#define SW_SZ   (C_*4*C_)
#define QW_SZ   (C_*3*C_)
#define PW_SZ   (C_*C_)
#define F1_SZ   (C_*HM_)
#define F2_SZ   (HM_*C_)

// ---------------- device scratch ----------------
__device__ float  g_x   [B_*N_*C_];          // residual stream (fp32)
__device__ __half g_h   [B_*N_*C_];          // LN output (fp16)
__device__ __half g_qkv [B_*N_*3*C_];        // qkv (fp16)
__device__ __half g_o   [B_*N_*C_];          // attention output (fp16)
__device__ __half g_mlp [B_*N_*HM_];         // fc1 output (fp16)
__device__ __half g_tok [B_*SPLN*C_];        // gathered top tokens (fp16)
__device__ int    g_ord [B_*NTOK];
__device__ float  g_glb [B_*(N_-1)];
__device__ float  g_cls [B_*(N_-1)];
// fp16 weights
__device__ __half g_wsplit[SW_SZ];
__device__ __half g_wqkv  [L_*QW_SZ];
__device__ __half g_wproj [L_*PW_SZ];
__device__ __half g_wfc1  [L_*F1_SZ];
__device__ __half g_wfc2  [L_*F2_SZ];

// ---------------- helpers ----------------
__device__ __forceinline__ uint32_t smem_u32(const void* p) {
    uint32_t a;
    asm("{ .reg .u64 t; cvta.to.shared.u64 t, %1; cvt.u32.u64 %0, t; }" : "=r"(a) : "l"(p));
    return a;
}
__device__ __forceinline__ void mma_f16(float& c0, float& c1, float& c2, float& c3,
                                        uint32_t a0, uint32_t a1, uint32_t a2, uint32_t a3,
                                        uint32_t b0, uint32_t b1) {
    asm volatile("mma.sync.aligned.m16n8k16.row.col.f32.f16.f16.f32 "
                 "{%0,%1,%2,%3}, {%4,%5,%6,%7}, {%8,%9}, {%0,%1,%2,%3};"
                 : "+f"(c0), "+f"(c1), "+f"(c2), "+f"(c3)
                 : "r"(a0), "r"(a1), "r"(a2), "r"(a3), "r"(b0), "r"(b1));
}
__device__ __forceinline__ void ldsm_x4(uint32_t& r0, uint32_t& r1, uint32_t& r2, uint32_t& r3,
                                        uint32_t addr) {
    asm volatile("ldmatrix.sync.aligned.m8n8.x4.shared.b16 {%0,%1,%2,%3}, [%4];"
                 : "=r"(r0), "=r"(r1), "=r"(r2), "=r"(r3) : "r"(addr));
}
__device__ __forceinline__ void ldsm_x4_t(uint32_t& r0, uint32_t& r1, uint32_t& r2, uint32_t& r3,
                                          uint32_t addr) {
    asm volatile("ldmatrix.sync.aligned.m8n8.x4.trans.shared.b16 {%0,%1,%2,%3}, [%4];"
                 : "=r"(r0), "=r"(r1), "=r"(r2), "=r"(r3) : "r"(addr));
}
__device__ __forceinline__ void cp16(uint32_t dst, const void* src, int sz) {
    asm volatile("cp.async.cg.shared.global [%0], [%1], 16, %2;"
                 :: "r"(dst), "l"(src), "r"(sz) : "memory");
}
#define CP_COMMIT() asm volatile("cp.async.commit_group;" ::: "memory")
#define CP_WAIT1()  asm volatile("cp.async.wait_group 1;" ::: "memory")
#define CP_WAIT0()  asm volatile("cp.async.wait_group 0;" ::: "memory")

// ---------------- weight convert fp32 -> fp16 ----------------
__global__ void wconv_kernel(const float* __restrict__ src, __half* __restrict__ dst, int n) {
    int stride = gridDim.x * blockDim.x;
    for (int i = blockIdx.x*blockDim.x + threadIdx.x; i < n; i += stride)
        dst[i] = __float2half_rn(src[i]);
}

// ---------------- sort ----------------
__global__ void sort_kernel(const float* __restrict__ attn) {
    __shared__ float sv[256];
    __shared__ int   si[256];
    int b = blockIdx.x, t = threadIdx.x;
    sv[t] = (t < NTOK) ? attn[b*NTOK + t] : -INFINITY;
    si[t] = t;
    __syncthreads();
    for (int k = 2; k <= 256; k <<= 1) {
        for (int j = k >> 1; j > 0; j >>= 1) {
            int ix = t ^ j;
            if (ix > t) {
                float v1 = sv[t], v2 = sv[ix];
                int   i1 = si[t], i2 = si[ix];
                bool before = (v1 > v2) || (v1 == v2 && i1 < i2);
                bool doswap = ((t & k) == 0) ? (!before) : before;
                if (doswap) { sv[t]=v2; sv[ix]=v1; si[t]=i2; si[ix]=i1; }
            }
            __syncthreads();
        }
    }
    if (t < NTOK) g_ord[b*NTOK + t] = si[t];
}

// ---------------- gather ----------------
__global__ void gather_kernel(const float* __restrict__ xin) {
    int blk = blockIdx.x;
    int b = blk / 197, r = blk % 197;
    int t = threadIdx.x;
    if (r == 0) {
        const float* srow = xin + (size_t)b*197*C_;
        float* drow = g_x + (size_t)b*N_*C_;
        drow[t] = srow[t]; drow[t+256] = srow[t+256]; drow[t+512] = srow[t+512];
    } else if (r <= SPLN) {
        int i = r - 1;
        int ord = g_ord[b*NTOK + i];
        const float* srow = xin + ((size_t)b*197 + 1 + ord)*C_;
        __half* drow = g_tok + ((size_t)b*SPLN + i)*C_;
        drow[t]     = __float2half_rn(srow[t]);
        drow[t+256] = __float2half_rn(srow[t+256]);
        drow[t+512] = __float2half_rn(srow[t+512]);
    } else {
        int i = r - 1 - SPLN;
        int ord = g_ord[b*NTOK + SPLN + i];
        const float* srow = xin + ((size_t)b*197 + 1 + ord)*C_;
        float* drow = g_x + ((size_t)b*N_ + 1 + SPLN*4 + i)*C_;
        drow[t] = srow[t]; drow[t+256] = srow[t+256]; drow[t+512] = srow[t+512];
    }
}

__global__ void init_kernel() {
    int i = blockIdx.x*blockDim.x + threadIdx.x;
    if (i < B_*(N_-1)) { g_glb[i] = 0.f; g_cls[i] = 0.f; }
}

// ---------------- fp16 tensor-core GEMM: 128x128 tile, BK=32, warp 64x32, 3-stage cp.async ----
// modes: 0 bias->f32 | 1 bias+gelu->HALF | 2 bias+residual->f32 | 3 bias+split-remap->f32 | 4 bias->HALF
#define A_ST 40              // halves per A row (32 + 8 pad)
#define W_ST 136             // halves per W row (128 + 8 pad)
#define A_BY (128*A_ST*2)
#define W_BY (32*W_ST*2)
#define BUF_BY (A_BY + W_BY)
#define NSTAGE 3
#define GEMM_SMEM (NSTAGE*BUF_BY)

__global__ __launch_bounds__(256, 2)
void gemm_h(const __half* __restrict__ A, const __half* __restrict__ W,
            const float* __restrict__ bias, const float* __restrict__ resid,
            void* __restrict__ out, int M, int N, int K, int mode) {
    extern __shared__ char smc[];
    int tid  = threadIdx.x;
    int m0   = blockIdx.y * 128, n0 = blockIdx.x * 128;
    int warp = tid >> 5, lane = tid & 31;
    int g    = lane >> 2, tig = lane & 3;
    int wm0  = (warp >> 2) * 64;
    int wn0  = (warp & 3) * 32;

    uint32_t sbase = smem_u32(smc);

    float acc[4][4][4];
#pragma unroll
    for (int i = 0; i < 4; i++)
#pragma unroll
        for (int j = 0; j < 4; j++)
#pragma unroll
            for (int c = 0; c < 4; c++) acc[i][j][c] = 0.f;

    int nt = K >> 5;

#define ISSUE_TILE(kc_, buf_) do {                                              \
        uint32_t ab = sbase + (uint32_t)(buf_) * BUF_BY;                        \
        uint32_t wb = ab + A_BY;                                               \
        {                                                                       \
            int row = tid >> 1, c = tid & 1;                                    \
            int gr = m0 + row;                                                  \
            int ok = (gr < M);                                                  \
            const __half* src = A + (size_t)(ok ? gr : 0)*K + (kc_)*32 + c*16;  \
            uint32_t d = ab + (uint32_t)row*(A_ST*2) + (uint32_t)c*32;          \
            cp16(d,      src,     ok ? 16 : 0);                                 \
            cp16(d + 16, src + 8, ok ? 16 : 0);                                 \
        }                                                                       \
        {                                                                       \
            int kr = tid >> 3, seg = tid & 7;                                   \
            const __half* src = W + (size_t)((kc_)*32 + kr)*N + n0 + seg*16;    \
            uint32_t d = wb + (uint32_t)kr*(W_ST*2) + (uint32_t)seg*32;         \
            cp16(d,      src,     16);                                          \
            cp16(d + 16, src + 8, 16);                                          \
        }                                                                       \
        CP_COMMIT();                                                            \
    } while (0)

    ISSUE_TILE(0, 0);
    if (nt > 1) ISSUE_TILE(1, 1);

    int a_row = lane & 15;
    int a_col = (lane >> 4) << 3;
    int b_krw = (lane & 7) + (((lane >> 4) & 1) << 3);
    int b_ncl = ((lane >> 3) & 1) << 3;

    for (int kc = 0; kc < nt; kc++) {
        int buf = kc % NSTAGE;
        if (kc == nt - 1) { CP_WAIT0(); } else { CP_WAIT1(); }
        __syncthreads();
        if (kc + 2 < nt) ISSUE_TILE(kc + 2, (kc + 2) % NSTAGE);

        uint32_t ab = sbase + (uint32_t)buf * BUF_BY;
        uint32_t wb = ab + A_BY;
#pragma unroll
        for (int ks = 0; ks < 2; ks++) {
            int k0 = ks * 16;
            uint32_t a[4][4], b[4][2];
#pragma unroll
            for (int mi = 0; mi < 4; mi++) {
                uint32_t addr = ab + (uint32_t)((wm0 + mi*16 + a_row)*A_ST + k0 + a_col)*2;
                ldsm_x4(a[mi][0], a[mi][1], a[mi][2], a[mi][3], addr);
            }
#pragma unroll
            for (int np = 0; np < 2; np++) {
                uint32_t addr = wb + (uint32_t)((k0 + b_krw)*W_ST + wn0 + np*16 + b_ncl)*2;
                uint32_t r0, r1, r2, r3;
                ldsm_x4_t(r0, r1, r2, r3, addr);
                b[np*2][0]   = r0; b[np*2][1]   = r2;
                b[np*2+1][0] = r1; b[np*2+1][1] = r3;
            }
#pragma unroll
            for (int mi = 0; mi < 4; mi++)
#pragma unroll
                for (int ni = 0; ni < 4; ni++)
                    mma_f16(acc[mi][ni][0], acc[mi][ni][1], acc[mi][ni][2], acc[mi][ni][3],
                            a[mi][0], a[mi][1], a[mi][2], a[mi][3],
                            b[ni][0], b[ni][1]);
        }
    }
#undef ISSUE_TILE

    // epilogue
#pragma unroll
    for (int mi = 0; mi < 4; mi++) {
#pragma unroll
        for (int half_ = 0; half_ < 2; half_++) {
            int row = m0 + wm0 + mi*16 + g + half_*8;
            if (row >= M) continue;
#pragma unroll
            for (int ni = 0; ni < 4; ni++) {
                int col = n0 + wn0 + ni*8 + tig*2;
                float v0 = acc[mi][ni][half_*2]     + bias[col];
                float v1 = acc[mi][ni][half_*2 + 1] + bias[col+1];
                if (mode == 1) {
                    v0 = 0.5f*v0*(1.0f + erff(v0*0.70710678118654752f));
                    v1 = 0.5f*v1*(1.0f + erff(v1*0.70710678118654752f));
                    *(__half2*)((__half*)out + (size_t)row*N + col) =
                        __floats2half2_rn(v0, v1);
                } else if (mode == 4) {
                    *(__half2*)((__half*)out + (size_t)row*N + col) =
                        __floats2half2_rn(v0, v1);
                } else if (mode == 2) {
                    const float* rrow = resid + (size_t)row*N;
                    v0 += rrow[col];
                    v1 += rrow[col+1];
                    *(float2*)((float*)out + (size_t)row*N + col) = make_float2(v0, v1);
                } else if (mode == 3) {
                    int bb = row / SPLN, s = row % SPLN;
                    float* orow = (float*)out + ((size_t)bb*N_ + 1 + (size_t)s*4)*C_;
                    *(float2*)(orow + col) = make_float2(v0, v1);
                } else {
                    *(float2*)((float*)out + (size_t)row*N + col) = make_float2(v0, v1);
                }
            }
        }
    }
}

// ---------------- layernorm (fp16 output) ----------------
__global__ __launch_bounds__(256)
void ln_kernel(const float* __restrict__ in, __half* __restrict__ out,
               const float* __restrict__ gamma, const float* __restrict__ beta) {
    int row = blockIdx.x, t = threadIdx.x;
    const float* xr = in + (size_t)row * C_;
    float v0 = xr[t], v1 = xr[t+256], v2 = xr[t+512];
    __shared__ float red[8];
    float s = v0 + v1 + v2;
#pragma unroll
    for (int o = 16; o; o >>= 1) s += __shfl_xor_sync(~0u, s, o);
    if ((t & 31) == 0) red[t >> 5] = s;
    __syncthreads();
    float tot = 0.f;
#pragma unroll
    for (int i = 0; i < 8; i++) tot += red[i];
    float mean = tot * (1.0f / C_);
    __syncthreads();
    float d0 = v0 - mean, d1 = v1 - mean, d2 = v2 - mean;
    float s2 = d0*d0 + d1*d1 + d2*d2;
#pragma unroll
    for (int o = 16; o; o >>= 1) s2 += __shfl_xor_sync(~0u, s2, o);
    if ((t & 31) == 0) red[t >> 5] = s2;
    __syncthreads();
    float tot2 = 0.f;
#pragma unroll
    for (int i = 0; i < 8; i++) tot2 += red[i];
    float inv = rsqrtf(tot2 * (1.0f / C_) + 1e-6f);
    __half* orow = out + (size_t)row * C_;
    orow[t]       = __float2half_rn(d0 * inv * gamma[t]       + beta[t]);
    orow[t + 256] = __float2half_rn(d1 * inv * gamma[t + 256] + beta[t + 256]);
    orow[t + 512] = __float2half_rn(d2 * inv * gamma[t + 512] + beta[t + 512]);
}

// ---------------- fp16 flash attention, 128 q-rows per CTA ----------------
// smem (halves): Q [128][72] @0 ; K 2x[64][72] @9216 ; V 2x[64][72] @18432 ; P [128][72] @27648
#define FA_SMEM 73728
__global__ __launch_bounds__(256)
void flash_attn(const __half* __restrict__ qkv, __half* __restrict__ obuf) {
    extern __shared__ __half sh[];
    __half* Qs = sh;
    __half* Kh = sh + 9216;
    __half* Vh = sh + 18432;
    __half* Ps = sh + 27648;

    int bh = blockIdx.y;
    int b = bh / H_, h = bh % H_;
    int q0 = blockIdx.x * 128;
    int tid = threadIdx.x, warp = tid >> 5, lane = tid & 31;
    int g = lane >> 2, tig = lane & 3;
    const __half* base = qkv + (size_t)b * N_ * (3*C_) + h * D_;
    uint32_t sb = smem_u32(sh);

    // Q tile: 128 rows x 64 halves
    {
        const uint4 z = make_uint4(0,0,0,0);
        for (int idx = tid; idx < 128*8; idx += 256) {
            int r = idx >> 3, c8 = idx & 7;
            int qr = q0 + r;
            uint4 v = z;
            if (qr < N_) v = *(const uint4*)(base + (size_t)qr*(3*C_) + c8*8);
            *(uint4*)(Qs + r*72 + c8*8) = v;
        }
    }

#define FA_ISSUE(kt_, buf_) do {                                              \
        uint32_t kb8 = sb + (uint32_t)(9216 + (buf_)*4608)*2u;                \
        uint32_t vb8 = sb + (uint32_t)(18432 + (buf_)*4608)*2u;               \
        _Pragma("unroll")                                                     \
        for (int it = 0; it < 2; it++) {                                      \
            int chunk = tid + it*256;                                         \
            int r = chunk >> 3, c8 = chunk & 7;                               \
            int kr = (kt_)*64 + r;                                            \
            int ok = (kr < N_);                                               \
            const __half* ksrc = base + (size_t)(ok ? kr : 0)*(3*C_) + C_   + c8*8; \
            const __half* vsrc = base + (size_t)(ok ? kr : 0)*(3*C_) + 2*C_ + c8*8; \
            cp16(kb8 + (uint32_t)(r*72 + c8*8)*2u, ksrc, ok ? 16 : 0);        \
            cp16(vb8 + (uint32_t)(r*72 + c8*8)*2u, vsrc, ok ? 16 : 0);        \
        }                                                                     \
        CP_COMMIT();                                                          \
    } while (0)

    FA_ISSUE(0, 0);
    FA_ISSUE(1, 1);

    float o[8][4];
#pragma unroll
    for (int i = 0; i < 8; i++) { o[i][0]=0.f; o[i][1]=0.f; o[i][2]=0.f; o[i][3]=0.f; }
    float mr0 = -INFINITY, mr1 = -INFINITY, l0 = 0.f, l1 = 0.f;

    __half* Pw = Ps + warp*16*72;
    const __half* Qw = Qs + warp*16*72;

    int a_row = lane & 15;
    int a_col = (lane >> 4) << 3;
    int kb_nrow = (lane & 7) + ((lane >> 4) << 3);   // K (B, non-trans): n row
    int kb_koff = ((lane >> 3) & 1) << 3;            // K: k offset
    int vb_krw  = (lane & 7) + (((lane >> 4) & 1) << 3); // V (B, trans): k row
    int vb_ncl  = ((lane >> 3) & 1) << 3;                // V: n offset

    uint32_t Qw_s = sb + (uint32_t)(warp*16*72)*2u;
    uint32_t Pw_s = sb + (uint32_t)(27648 + warp*16*72)*2u;

    for (int kt = 0; kt < 8; kt++) {
        int buf = kt & 1;
        if (kt == 7) { CP_WAIT0(); } else { CP_WAIT1(); }
        __syncthreads();
        uint32_t Kt_s = sb + (uint32_t)(9216  + buf*4608)*2u;
        uint32_t Vt_s = sb + (uint32_t)(18432 + buf*4608)*2u;

        // S = Q K^T : m16 x n64 x k64
        float s[8][4];
#pragma unroll
        for (int i = 0; i < 8; i++) { s[i][0]=0.f; s[i][1]=0.f; s[i][2]=0.f; s[i][3]=0.f; }
#pragma unroll
        for (int ks = 0; ks < 4; ks++) {
            int k0 = ks * 16;
            uint32_t a0, a1, a2, a3;
            ldsm_x4(a0, a1, a2, a3, Qw_s + (uint32_t)(a_row*72 + k0 + a_col)*2u);
#pragma unroll
            for (int np = 0; np < 4; np++) {
                int nb = np * 16;
                uint32_t r0, r1, r2, r3;
                ldsm_x4(r0, r1, r2, r3, Kt_s + (uint32_t)((nb + kb_nrow)*72 + k0 + kb_koff)*2u);
                mma_f16(s[np*2][0],   s[np*2][1],   s[np*2][2],   s[np*2][3],   a0,a1,a2,a3, r0, r1);
                mma_f16(s[np*2+1][0], s[np*2+1][1], s[np*2+1][2], s[np*2+1][3], a0,a1,a2,a3, r2, r3);
            }
        }
        // scale + mask + online softmax (rows g, g+8)
        float mc0 = -INFINITY, mc1 = -INFINITY;
#pragma unroll
        for (int ni = 0; ni < 8; ni++) {
            int colb = kt*64 + ni*8 + 2*tig;
#pragma unroll
            for (int cc = 0; cc < 4; cc++) {
                float v = s[ni][cc] * 0.125f;
                if (colb + (cc & 1) >= N_) v = -INFINITY;
                s[ni][cc] = v;
                if (cc < 2) mc0 = fmaxf(mc0, v); else mc1 = fmaxf(mc1, v);
            }
        }
        mc0 = fmaxf(mc0, __shfl_xor_sync(~0u, mc0, 1));
        mc0 = fmaxf(mc0, __shfl_xor_sync(~0u, mc0, 2));
        mc1 = fmaxf(mc1, __shfl_xor_sync(~0u, mc1, 1));
        mc1 = fmaxf(mc1, __shfl_xor_sync(~0u, mc1, 2));
        float mn0 = fmaxf(mr0, mc0), mn1 = fmaxf(mr1, mc1);
        float al0 = expf(mr0 - mn0), al1 = expf(mr1 - mn1);
        mr0 = mn0; mr1 = mn1;
        float ls0 = 0.f, ls1 = 0.f;
#pragma unroll
        for (int ni = 0; ni < 8; ni++) {
            float p0 = expf(s[ni][0] - mn0);
            float p1 = expf(s[ni][1] - mn0);
            float p2 = expf(s[ni][2] - mn1);
            float p3 = expf(s[ni][3] - mn1);
            s[ni][0]=p0; s[ni][1]=p1; s[ni][2]=p2; s[ni][3]=p3;
            ls0 += p0 + p1; ls1 += p2 + p3;
        }
        ls0 += __shfl_xor_sync(~0u, ls0, 1); ls0 += __shfl_xor_sync(~0u, ls0, 2);
        ls1 += __shfl_xor_sync(~0u, ls1, 1); ls1 += __shfl_xor_sync(~0u, ls1, 2);
        l0 = l0*al0 + ls0; l1 = l1*al1 + ls1;

        __syncwarp();
        // P -> smem (fp16)
#pragma unroll
        for (int ni = 0; ni < 8; ni++) {
            *(__half2*)(Pw + g*72     + ni*8 + 2*tig) = __floats2half2_rn(s[ni][0], s[ni][1]);
            *(__half2*)(Pw + (g+8)*72 + ni*8 + 2*tig) = __floats2half2_rn(s[ni][2], s[ni][3]);
        }
#pragma unroll
        for (int ni = 0; ni < 8; ni++) {
            o[ni][0]*=al0; o[ni][1]*=al0; o[ni][2]*=al1; o[ni][3]*=al1;
        }
        __syncwarp();
        // O += P V : m16 x n64 x k64
#pragma unroll
        for (int ks = 0; ks < 4; ks++) {
            int k0 = ks * 16;
            uint32_t a0, a1, a2, a3;
            ldsm_x4(a0, a1, a2, a3, Pw_s + (uint32_t)(a_row*72 + k0 + a_col)*2u);
#pragma unroll
            for (int np = 0; np < 4; np++) {
                int nb = np * 16;
                uint32_t r0, r1, r2, r3;
                ldsm_x4_t(r0, r1, r2, r3, Vt_s + (uint32_t)((k0 + vb_krw)*72 + nb + vb_ncl)*2u);
                mma_f16(o[np*2][0],   o[np*2][1],   o[np*2][2],   o[np*2][3],   a0,a1,a2,a3, r0, r2);
                mma_f16(o[np*2+1][0], o[np*2+1][1], o[np*2+1][2], o[np*2+1][3], a0,a1,a2,a3, r1, r3);
            }
        }
        __syncthreads();
        if (kt + 2 < 8) FA_ISSUE(kt + 2, buf);
    }
#undef FA_ISSUE

    int r0 = q0 + warp*16 + g, r1 = r0 + 8;
    float inv0 = 1.f / l0, inv1 = 1.f / l1;
#pragma unroll
    for (int ni = 0; ni < 8; ni++) {
        int col = h*D_ + ni*8 + 2*tig;
        if (r0 < N_)
            *(__half2*)(obuf + ((size_t)b*N_ + r0)*C_ + col) =
                __floats2half2_rn(o[ni][0]*inv0, o[ni][1]*inv0);
        if (r1 < N_)
            *(__half2*)(obuf + ((size_t)b*N_ + r1)*C_ + col) =
                __floats2half2_rn(o[ni][2]*inv1, o[ni][3]*inv1);
    }
}

// ---------------- cls attention row (fp32 softmax of q-row 0, fp16 inputs) ----------------
__global__ __launch_bounds__(256)
void cls_kernel(const __half* __restrict__ qkv, float* __restrict__ cls_acc) {
    __shared__ float q0s[64];
    __shared__ float red[8];
    int bh = blockIdx.x;
    int b = bh / H_, h = bh % H_;
    const __half* base = qkv + (size_t)b * N_ * (3*C_) + h * D_;
    int tid = threadIdx.x, lane = tid & 31, warp = tid >> 5;
    if (tid < 64) q0s[tid] = __half2float(base[tid]);
    __syncthreads();

    float s0 = -INFINITY, s1 = -INFINITY;
    {
        int j = tid;
        if (j < N_) {
            float a = 0.f;
            const __half* k = base + (size_t)j*(3*C_) + C_;
#pragma unroll 16
            for (int d = 0; d < 64; d++) a += q0s[d]*__half2float(k[d]);
            s0 = a * 0.125f;
        }
        j = tid + 256;
        if (j < N_) {
            float a = 0.f;
            const __half* k = base + (size_t)j*(3*C_) + C_;
#pragma unroll 16
            for (int d = 0; d < 64; d++) a += q0s[d]*__half2float(k[d]);
            s1 = a * 0.125f;
        }
    }
    float m = fmaxf(s0, s1);
#pragma unroll
    for (int off = 16; off; off >>= 1) m = fmaxf(m, __shfl_xor_sync(~0u, m, off));
    if (lane == 0) red[warp] = m;
    __syncthreads();
    float M = red[0];
#pragma unroll
    for (int i = 1; i < 8; i++) M = fmaxf(M, red[i]);
    __syncthreads();
    float e0 = expf(s0 - M), e1 = expf(s1 - M);
    float t = e0 + e1;
#pragma unroll
    for (int off = 16; off; off >>= 1) t += __shfl_xor_sync(~0u, t, off);
    if (lane == 0) red[warp] = t;
    __syncthreads();
    float L = 0.f;
#pragma unroll
    for (int i = 0; i < 8; i++) L += red[i];
    float invL = 1.f / (L * (float)H_);
    int j = tid;
    if (j >= 1 && j < N_) atomicAdd(&cls_acc[b*(N_-1) + j - 1], e0 * invL);
    j = tid + 256;
    if (j < N_) atomicAdd(&cls_acc[b*(N_-1) + j - 1], e1 * invL);
}

// ---------------- glb EMA ----------------
__global__ void glb_kernel() {
    int i = blockIdx.x*blockDim.x + threadIdx.x;
    if (i < B_*(N_-1)) {
        g_glb[i] = 0.5f * g_glb[i] + 0.5f * g_cls[i];
        g_cls[i] = 0.f;
    }
}

// ---------------- output ----------------
__global__ void copy_out_kernel(float* __restrict__ out, int out_size) {
    const int NX = B_*N_*C_;
    const int NG = B_*(N_-1);
    for (int i = blockIdx.x*blockDim.x + threadIdx.x; i < out_size;
         i += gridDim.x*blockDim.x) {
        float v = 0.f;
        if (i < NX)            v = g_x[i];
        else if (i < NX + NG)  v = g_glb[i - NX];
        out[i] = v;
    }
}

// ---------------- launch ----------------
extern "C" void kernel_launch(void* const* d_in, const int* in_sizes, int n_in,
                              void* d_out, int out_size) {
    const float* x       = (const float*)d_in[0];
    const float* gattn   = (const float*)d_in[1];
    const float* split_w = (const float*)d_in[2];
    const float* split_b = (const float*)d_in[3];
    const float* ln1_g   = (const float*)d_in[4];
    const float* ln1_b   = (const float*)d_in[5];
    const float* qkv_w   = (const float*)d_in[6];
    const float* qkv_b   = (const float*)d_in[7];
    const float* proj_w  = (const float*)d_in[8];
    const float* proj_b  = (const float*)d_in[9];
    const float* ln2_g   = (const float*)d_in[10];
    const float* ln2_b   = (const float*)d_in[11];
    const float* fc1_w   = (const float*)d_in[12];
    const float* fc1_b   = (const float*)d_in[13];
    const float* fc2_w   = (const float*)d_in[14];
    const float* fc2_b   = (const float*)d_in[15];

    float *px, *pcls;
    __half *ph, *pqkv, *po, *pmlp, *ptok;
    __half *pwsplit, *pwqkv, *pwproj, *pwfc1, *pwfc2;
    cudaGetSymbolAddress((void**)&px,   g_x);
    cudaGetSymbolAddress((void**)&ph,   g_h);
    cudaGetSymbolAddress((void**)&pqkv, g_qkv);
    cudaGetSymbolAddress((void**)&po,   g_o);
    cudaGetSymbolAddress((void**)&pmlp, g_mlp);
    cudaGetSymbolAddress((void**)&ptok, g_tok);
    cudaGetSymbolAddress((void**)&pcls, g_cls);
    cudaGetSymbolAddress((void**)&pwsplit, g_wsplit);
    cudaGetSymbolAddress((void**)&pwqkv,   g_wqkv);
    cudaGetSymbolAddress((void**)&pwproj,  g_wproj);
    cudaGetSymbolAddress((void**)&pwfc1,   g_wfc1);
    cudaGetSymbolAddress((void**)&pwfc2,   g_wfc2);

    cudaFuncSetAttribute(gemm_h,     cudaFuncAttributeMaxDynamicSharedMemorySize, GEMM_SMEM);
    cudaFuncSetAttribute(flash_attn, cudaFuncAttributeMaxDynamicSharedMemorySize, FA_SMEM);

    // order chosen so ncu (-s 5 -c 1) captures the split GEMM (launch idx 5)
    wconv_kernel<<<2048, 256>>>(split_w, pwsplit, SW_SZ);                 // 0
    sort_kernel<<<B_, 256>>>(gattn);                                      // 1
    gather_kernel<<<B_*197, 256>>>(x);                                    // 2
    init_kernel<<<(B_*(N_-1) + 255)/256, 256>>>();                        // 3
    wconv_kernel<<<2048, 256>>>(qkv_w,   pwqkv,   L_*QW_SZ);              // 4
    {   // 5: split GEMM  M=1568, N=3072, K=768
        int M = B_*SPLN, N = 4*C_, K = C_;
        dim3 grid(N/128, (M + 127)/128);
        gemm_h<<<grid, 256, GEMM_SMEM>>>(ptok, pwsplit, split_b, nullptr, px, M, N, K, 3);
    }
    wconv_kernel<<<2048, 256>>>(proj_w,  pwproj,  L_*PW_SZ);
    wconv_kernel<<<2048, 256>>>(fc1_w,   pwfc1,   L_*F1_SZ);
    wconv_kernel<<<2048, 256>>>(fc2_w,   pwfc2,   L_*F2_SZ);

    for (int l = 0; l < L_; l++) {
        const float* l1g = ln1_g + l*C_;
        const float* l1b = ln1_b + l*C_;
        const __half* qw = pwqkv + (size_t)l*QW_SZ;
        const float* qb  = qkv_b + l*3*C_;
        const __half* pw = pwproj + (size_t)l*PW_SZ;
        const float* pb  = proj_b + l*C_;
        const float* l2g = ln2_g + l*C_;
        const float* l2b = ln2_b + l*C_;
        const __half* w1 = pwfc1 + (size_t)l*F1_SZ;
        const float* b1  = fc1_b + l*HM_;
        const __half* w2 = pwfc2 + (size_t)l*F2_SZ;
        const float* b2  = fc2_b + l*C_;

        ln_kernel<<<M_ROWS, 256>>>(px, ph, l1g, l1b);

        { dim3 grid((3*C_)/128, (M_ROWS + 127)/128);
          gemm_h<<<grid, 256, GEMM_SMEM>>>(ph, qw, qb, nullptr, pqkv, M_ROWS, 3*C_, C_, 4); }

        cls_kernel<<<B_*H_, 256>>>(pqkv, pcls);

        { dim3 grid(4, B_*H_);
          flash_attn<<<grid, 256, FA_SMEM>>>(pqkv, po); }

        glb_kernel<<<(B_*(N_-1) + 255)/256, 256>>>();

        { dim3 grid(C_/128, (M_ROWS + 127)/128);
          gemm_h<<<grid, 256, GEMM_SMEM>>>(po, pw, pb, px, px, M_ROWS, C_, C_, 2); }

        ln_kernel<<<M_ROWS, 256>>>(px, ph, l2g, l2b);

        { dim3 grid(HM_/128, (M_ROWS + 127)/128);
          gemm_h<<<grid, 256, GEMM_SMEM>>>(ph, w1, b1, nullptr, pmlp, M_ROWS, HM_, C_, 1); }

        { dim3 grid(C_/128, (M_ROWS + 127)/128);
          gemm_h<<<grid, 256, GEMM_SMEM>>>(pmlp, w2, b2, px, px, M_ROWS, C_, HM_, 2); }
    }

    copy_out_kernel<<<2048, 256>>>((float*)d_out, out_size);
}

// round 10
// speedup vs baseline: 1.6806x; 1.0187x over previous
#include <cuda_runtime.h>
#include <cuda_fp16.h>
#include <math.h>
#include <stdint.h>

// ---------------- problem constants ----------------
#define B_    16
#define NTOK  196
#define SPLN  98
#define N_    491          // 1 + 98*4 + 98
#define C_    768
#define HM_   3072
#define H_    12
#define D_    64
#define L_    4
#define M_ROWS (B_*N_)     // 7856

// weight sizes
#define SW_SZ   (C_*4*C_)
#define QW_SZ   (C_*3*C_)
#define PW_SZ   (C_*C_)
#define F1_SZ   (C_*HM_)
#define F2_SZ   (HM_*C_)

// ---------------- device scratch ----------------
__device__ float  g_x   [B_*N_*C_];          // residual stream (fp32)
__device__ __half g_h   [B_*N_*C_];          // LN output (fp16)
__device__ __half g_qkv [B_*N_*3*C_];        // qkv (fp16)
__device__ __half g_o   [B_*N_*C_];          // attention output (fp16)
__device__ __half g_mlp [B_*N_*HM_];         // fc1 output (fp16)
__device__ __half g_tok [B_*SPLN*C_];        // gathered top tokens (fp16)
__device__ int    g_ord [B_*NTOK];
__device__ float  g_glb [B_*(N_-1)];
__device__ float  g_cls [B_*(N_-1)];
// fp16 weights
__device__ __half g_wsplit[SW_SZ];
__device__ __half g_wqkv  [L_*QW_SZ];
__device__ __half g_wproj [L_*PW_SZ];
__device__ __half g_wfc1  [L_*F1_SZ];
__device__ __half g_wfc2  [L_*F2_SZ];

// ---------------- helpers ----------------
__device__ __forceinline__ uint32_t smem_u32(const void* p) {
    uint32_t a;
    asm("{ .reg .u64 t; cvta.to.shared.u64 t, %1; cvt.u32.u64 %0, t; }" : "=r"(a) : "l"(p));
    return a;
}
__device__ __forceinline__ void mma_f16(float& c0, float& c1, float& c2, float& c3,
                                        uint32_t a0, uint32_t a1, uint32_t a2, uint32_t a3,
                                        uint32_t b0, uint32_t b1) {
    asm volatile("mma.sync.aligned.m16n8k16.row.col.f32.f16.f16.f32 "
                 "{%0,%1,%2,%3}, {%4,%5,%6,%7}, {%8,%9}, {%0,%1,%2,%3};"
                 : "+f"(c0), "+f"(c1), "+f"(c2), "+f"(c3)
                 : "r"(a0), "r"(a1), "r"(a2), "r"(a3), "r"(b0), "r"(b1));
}
__device__ __forceinline__ void ldsm_x4(uint32_t& r0, uint32_t& r1, uint32_t& r2, uint32_t& r3,
                                        uint32_t addr) {
    asm volatile("ldmatrix.sync.aligned.m8n8.x4.shared.b16 {%0,%1,%2,%3}, [%4];"
                 : "=r"(r0), "=r"(r1), "=r"(r2), "=r"(r3) : "r"(addr));
}
__device__ __forceinline__ void ldsm_x4_t(uint32_t& r0, uint32_t& r1, uint32_t& r2, uint32_t& r3,
                                          uint32_t addr) {
    asm volatile("ldmatrix.sync.aligned.m8n8.x4.trans.shared.b16 {%0,%1,%2,%3}, [%4];"
                 : "=r"(r0), "=r"(r1), "=r"(r2), "=r"(r3) : "r"(addr));
}
__device__ __forceinline__ void cp16(uint32_t dst, const void* src, int sz) {
    asm volatile("cp.async.cg.shared.global [%0], [%1], 16, %2;"
                 :: "r"(dst), "l"(src), "r"(sz) : "memory");
}
#define CP_COMMIT() asm volatile("cp.async.commit_group;" ::: "memory")
#define CP_WAIT1()  asm volatile("cp.async.wait_group 1;" ::: "memory")
#define CP_WAIT0()  asm volatile("cp.async.wait_group 0;" ::: "memory")

// ---------------- weight convert fp32 -> fp16 ----------------
__global__ void wconv_kernel(const float* __restrict__ src, __half* __restrict__ dst, int n) {
    int stride = gridDim.x * blockDim.x;
    for (int i = blockIdx.x*blockDim.x + threadIdx.x; i < n; i += stride)
        dst[i] = __float2half_rn(src[i]);
}

// ---------------- sort ----------------
__global__ void sort_kernel(const float* __restrict__ attn) {
    __shared__ float sv[256];
    __shared__ int   si[256];
    int b = blockIdx.x, t = threadIdx.x;
    sv[t] = (t < NTOK) ? attn[b*NTOK + t] : -INFINITY;
    si[t] = t;
    __syncthreads();
    for (int k = 2; k <= 256; k <<= 1) {
        for (int j = k >> 1; j > 0; j >>= 1) {
            int ix = t ^ j;
            if (ix > t) {
                float v1 = sv[t], v2 = sv[ix];
                int   i1 = si[t], i2 = si[ix];
                bool before = (v1 > v2) || (v1 == v2 && i1 < i2);
                bool doswap = ((t & k) == 0) ? (!before) : before;
                if (doswap) { sv[t]=v2; sv[ix]=v1; si[t]=i2; si[ix]=i1; }
            }
            __syncthreads();
        }
    }
    if (t < NTOK) g_ord[b*NTOK + t] = si[t];
}

// ---------------- gather ----------------
__global__ void gather_kernel(const float* __restrict__ xin) {
    int blk = blockIdx.x;
    int b = blk / 197, r = blk % 197;
    int t = threadIdx.x;
    if (r == 0) {
        const float* srow = xin + (size_t)b*197*C_;
        float* drow = g_x + (size_t)b*N_*C_;
        drow[t] = srow[t]; drow[t+256] = srow[t+256]; drow[t+512] = srow[t+512];
    } else if (r <= SPLN) {
        int i = r - 1;
        int ord = g_ord[b*NTOK + i];
        const float* srow = xin + ((size_t)b*197 + 1 + ord)*C_;
        __half* drow = g_tok + ((size_t)b*SPLN + i)*C_;
        drow[t]     = __float2half_rn(srow[t]);
        drow[t+256] = __float2half_rn(srow[t+256]);
        drow[t+512] = __float2half_rn(srow[t+512]);
    } else {
        int i = r - 1 - SPLN;
        int ord = g_ord[b*NTOK + SPLN + i];
        const float* srow = xin + ((size_t)b*197 + 1 + ord)*C_;
        float* drow = g_x + ((size_t)b*N_ + 1 + SPLN*4 + i)*C_;
        drow[t] = srow[t]; drow[t+256] = srow[t+256]; drow[t+512] = srow[t+512];
    }
}

__global__ void init_kernel() {
    int i = blockIdx.x*blockDim.x + threadIdx.x;
    if (i < B_*(N_-1)) { g_glb[i] = 0.f; g_cls[i] = 0.f; }
}

// ---------------- fp16 tensor-core GEMM: 128x128 tile, BK=64, warp 64x32, 3-stage cp.async ----
// modes: 0 bias->f32 | 1 bias+gelu->HALF | 2 bias+residual->f32 | 3 bias+split-remap->f32 | 4 bias->HALF
#define A_ST 72              // halves per A row (64 + 8 pad)
#define W_ST 136             // halves per W row (128 + 8 pad)
#define A_BY (128*A_ST*2)    // 18432
#define W_BY (64*W_ST*2)     // 17408
#define BUF_BY (A_BY + W_BY) // 35840
#define NSTAGE 3
#define GEMM_SMEM (NSTAGE*BUF_BY)  // 107520

__global__ __launch_bounds__(256, 2)
void gemm_h(const __half* __restrict__ A, const __half* __restrict__ W,
            const float* __restrict__ bias, const float* __restrict__ resid,
            void* __restrict__ out, int M, int N, int K, int mode) {
    extern __shared__ char smc[];
    int tid  = threadIdx.x;
    int m0   = blockIdx.y * 128, n0 = blockIdx.x * 128;
    int warp = tid >> 5, lane = tid & 31;
    int g    = lane >> 2, tig = lane & 3;
    int wm0  = (warp >> 2) * 64;
    int wn0  = (warp & 3) * 32;

    uint32_t sbase = smem_u32(smc);

    float acc[4][4][4];
#pragma unroll
    for (int i = 0; i < 4; i++)
#pragma unroll
        for (int j = 0; j < 4; j++)
#pragma unroll
            for (int c = 0; c < 4; c++) acc[i][j][c] = 0.f;

    int nt = K >> 6;    // K multiple of 64 (768 / 3072)

#define ISSUE_TILE(kc_, buf_) do {                                              \
        uint32_t ab = sbase + (uint32_t)(buf_) * BUF_BY;                        \
        uint32_t wb = ab + A_BY;                                               \
        {   /* A: 128 rows x 64 halves */                                       \
            int row = tid >> 1, c = tid & 1;                                    \
            int gr = m0 + row;                                                  \
            int ok = (gr < M);                                                  \
            const __half* src = A + (size_t)(ok ? gr : 0)*K + (kc_)*64 + c*32;  \
            uint32_t d = ab + (uint32_t)row*(A_ST*2) + (uint32_t)c*64;          \
            cp16(d,      src,      ok ? 16 : 0);                                \
            cp16(d + 16, src + 8,  ok ? 16 : 0);                                \
            cp16(d + 32, src + 16, ok ? 16 : 0);                                \
            cp16(d + 48, src + 24, ok ? 16 : 0);                                \
        }                                                                       \
        {   /* W: 64 rows x 128 halves */                                       \
            int kr = tid >> 3, seg = tid & 7;                                   \
            _Pragma("unroll")                                                   \
            for (int rr = 0; rr < 2; rr++) {                                    \
                int r = kr + rr*32;                                             \
                const __half* src = W + (size_t)((kc_)*64 + r)*N + n0 + seg*16; \
                uint32_t d = wb + (uint32_t)r*(W_ST*2) + (uint32_t)seg*32;      \
                cp16(d,      src,     16);                                      \
                cp16(d + 16, src + 8, 16);                                      \
            }                                                                   \
        }                                                                       \
        CP_COMMIT();                                                            \
    } while (0)

    ISSUE_TILE(0, 0);
    ISSUE_TILE(1, 1);

    int a_row = lane & 15;
    int a_col = (lane >> 4) << 3;
    int b_krw = (lane & 7) + (((lane >> 4) & 1) << 3);
    int b_ncl = ((lane >> 3) & 1) << 3;

    for (int kc = 0; kc < nt; kc++) {
        int buf = kc % NSTAGE;
        if (kc == nt - 1) { CP_WAIT0(); } else { CP_WAIT1(); }
        __syncthreads();
        if (kc + 2 < nt) ISSUE_TILE(kc + 2, (kc + 2) % NSTAGE);

        uint32_t ab = sbase + (uint32_t)buf * BUF_BY;
        uint32_t wb = ab + A_BY;
#pragma unroll
        for (int ks = 0; ks < 4; ks++) {
            int k0 = ks * 16;
            uint32_t a[4][4], b[4][2];
#pragma unroll
            for (int mi = 0; mi < 4; mi++) {
                uint32_t addr = ab + (uint32_t)((wm0 + mi*16 + a_row)*A_ST + k0 + a_col)*2;
                ldsm_x4(a[mi][0], a[mi][1], a[mi][2], a[mi][3], addr);
            }
#pragma unroll
            for (int np = 0; np < 2; np++) {
                uint32_t addr = wb + (uint32_t)((k0 + b_krw)*W_ST + wn0 + np*16 + b_ncl)*2;
                uint32_t r0, r1, r2, r3;
                ldsm_x4_t(r0, r1, r2, r3, addr);
                b[np*2][0]   = r0; b[np*2][1]   = r2;
                b[np*2+1][0] = r1; b[np*2+1][1] = r3;
            }
#pragma unroll
            for (int mi = 0; mi < 4; mi++)
#pragma unroll
                for (int ni = 0; ni < 4; ni++)
                    mma_f16(acc[mi][ni][0], acc[mi][ni][1], acc[mi][ni][2], acc[mi][ni][3],
                            a[mi][0], a[mi][1], a[mi][2], a[mi][3],
                            b[ni][0], b[ni][1]);
        }
    }
#undef ISSUE_TILE

    // epilogue
#pragma unroll
    for (int mi = 0; mi < 4; mi++) {
#pragma unroll
        for (int half_ = 0; half_ < 2; half_++) {
            int row = m0 + wm0 + mi*16 + g + half_*8;
            if (row >= M) continue;
#pragma unroll
            for (int ni = 0; ni < 4; ni++) {
                int col = n0 + wn0 + ni*8 + tig*2;
                float v0 = acc[mi][ni][half_*2]     + bias[col];
                float v1 = acc[mi][ni][half_*2 + 1] + bias[col+1];
                if (mode == 1) {
                    v0 = 0.5f*v0*(1.0f + erff(v0*0.70710678118654752f));
                    v1 = 0.5f*v1*(1.0f + erff(v1*0.70710678118654752f));
                    *(__half2*)((__half*)out + (size_t)row*N + col) =
                        __floats2half2_rn(v0, v1);
                } else if (mode == 4) {
                    *(__half2*)((__half*)out + (size_t)row*N + col) =
                        __floats2half2_rn(v0, v1);
                } else if (mode == 2) {
                    const float* rrow = resid + (size_t)row*N;
                    v0 += rrow[col];
                    v1 += rrow[col+1];
                    *(float2*)((float*)out + (size_t)row*N + col) = make_float2(v0, v1);
                } else if (mode == 3) {
                    int bb = row / SPLN, s = row % SPLN;
                    float* orow = (float*)out + ((size_t)bb*N_ + 1 + (size_t)s*4)*C_;
                    *(float2*)(orow + col) = make_float2(v0, v1);
                } else {
                    *(float2*)((float*)out + (size_t)row*N + col) = make_float2(v0, v1);
                }
            }
        }
    }
}

// ---------------- layernorm: warp per row (8 rows / 256-thread block) ----------------
__global__ __launch_bounds__(256)
void ln_kernel(const float* __restrict__ in, __half* __restrict__ out,
               const float* __restrict__ gamma, const float* __restrict__ beta) {
    int warp = threadIdx.x >> 5, lane = threadIdx.x & 31;
    int row = blockIdx.x * 8 + warp;
    if (row >= M_ROWS) return;
    const float4* xr = (const float4*)(in + (size_t)row * C_);
    float4 v[6];
    float s = 0.f;
#pragma unroll
    for (int i = 0; i < 6; i++) {
        v[i] = xr[lane + i*32];
        s += v[i].x + v[i].y + v[i].z + v[i].w;
    }
#pragma unroll
    for (int o = 16; o; o >>= 1) s += __shfl_xor_sync(~0u, s, o);
    float mean = s * (1.0f / C_);
    float s2 = 0.f;
#pragma unroll
    for (int i = 0; i < 6; i++) {
        float a = v[i].x - mean, b = v[i].y - mean, c = v[i].z - mean, d = v[i].w - mean;
        s2 += a*a + b*b + c*c + d*d;
    }
#pragma unroll
    for (int o = 16; o; o >>= 1) s2 += __shfl_xor_sync(~0u, s2, o);
    float inv = rsqrtf(s2 * (1.0f / C_) + 1e-6f);
    __half2* orow = (__half2*)(out + (size_t)row * C_);
#pragma unroll
    for (int i = 0; i < 6; i++) {
        int c0 = (lane + i*32) * 4;
        float4 gm = *(const float4*)(gamma + c0);
        float4 bt = *(const float4*)(beta  + c0);
        orow[c0/2]     = __floats2half2_rn((v[i].x - mean)*inv*gm.x + bt.x,
                                           (v[i].y - mean)*inv*gm.y + bt.y);
        orow[c0/2 + 1] = __floats2half2_rn((v[i].z - mean)*inv*gm.z + bt.z,
                                           (v[i].w - mean)*inv*gm.w + bt.w);
    }
}

// ---------------- fp16 flash attention, 128 q-rows per CTA ----------------
#define FA_SMEM 73728
__global__ __launch_bounds__(256)
void flash_attn(const __half* __restrict__ qkv, __half* __restrict__ obuf) {
    extern __shared__ __half sh[];
    __half* Qs = sh;
    __half* Ps = sh + 27648;

    int bh = blockIdx.y;
    int b = bh / H_, h = bh % H_;
    int q0 = blockIdx.x * 128;
    int tid = threadIdx.x, warp = tid >> 5, lane = tid & 31;
    int g = lane >> 2, tig = lane & 3;
    const __half* base = qkv + (size_t)b * N_ * (3*C_) + h * D_;
    uint32_t sb = smem_u32(sh);

    {
        const uint4 z = make_uint4(0,0,0,0);
        for (int idx = tid; idx < 128*8; idx += 256) {
            int r = idx >> 3, c8 = idx & 7;
            int qr = q0 + r;
            uint4 v = z;
            if (qr < N_) v = *(const uint4*)(base + (size_t)qr*(3*C_) + c8*8);
            *(uint4*)(Qs + r*72 + c8*8) = v;
        }
    }

#define FA_ISSUE(kt_, buf_) do {                                              \
        uint32_t kb8 = sb + (uint32_t)(9216 + (buf_)*4608)*2u;                \
        uint32_t vb8 = sb + (uint32_t)(18432 + (buf_)*4608)*2u;               \
        _Pragma("unroll")                                                     \
        for (int it = 0; it < 2; it++) {                                      \
            int chunk = tid + it*256;                                         \
            int r = chunk >> 3, c8 = chunk & 7;                               \
            int kr = (kt_)*64 + r;                                            \
            int ok = (kr < N_);                                               \
            const __half* ksrc = base + (size_t)(ok ? kr : 0)*(3*C_) + C_   + c8*8; \
            const __half* vsrc = base + (size_t)(ok ? kr : 0)*(3*C_) + 2*C_ + c8*8; \
            cp16(kb8 + (uint32_t)(r*72 + c8*8)*2u, ksrc, ok ? 16 : 0);        \
            cp16(vb8 + (uint32_t)(r*72 + c8*8)*2u, vsrc, ok ? 16 : 0);        \
        }                                                                     \
        CP_COMMIT();                                                          \
    } while (0)

    FA_ISSUE(0, 0);
    FA_ISSUE(1, 1);

    float o[8][4];
#pragma unroll
    for (int i = 0; i < 8; i++) { o[i][0]=0.f; o[i][1]=0.f; o[i][2]=0.f; o[i][3]=0.f; }
    float mr0 = -INFINITY, mr1 = -INFINITY, l0 = 0.f, l1 = 0.f;

    __half* Pw = Ps + warp*16*72;

    int a_row = lane & 15;
    int a_col = (lane >> 4) << 3;
    int kb_nrow = (lane & 7) + ((lane >> 4) << 3);
    int kb_koff = ((lane >> 3) & 1) << 3;
    int vb_krw  = (lane & 7) + (((lane >> 4) & 1) << 3);
    int vb_ncl  = ((lane >> 3) & 1) << 3;

    uint32_t Qw_s = sb + (uint32_t)(warp*16*72)*2u;
    uint32_t Pw_s = sb + (uint32_t)(27648 + warp*16*72)*2u;

    for (int kt = 0; kt < 8; kt++) {
        int buf = kt & 1;
        if (kt == 7) { CP_WAIT0(); } else { CP_WAIT1(); }
        __syncthreads();
        uint32_t Kt_s = sb + (uint32_t)(9216  + buf*4608)*2u;
        uint32_t Vt_s = sb + (uint32_t)(18432 + buf*4608)*2u;

        float s[8][4];
#pragma unroll
        for (int i = 0; i < 8; i++) { s[i][0]=0.f; s[i][1]=0.f; s[i][2]=0.f; s[i][3]=0.f; }
#pragma unroll
        for (int ks = 0; ks < 4; ks++) {
            int k0 = ks * 16;
            uint32_t a0, a1, a2, a3;
            ldsm_x4(a0, a1, a2, a3, Qw_s + (uint32_t)(a_row*72 + k0 + a_col)*2u);
#pragma unroll
            for (int np = 0; np < 4; np++) {
                int nb = np * 16;
                uint32_t r0, r1, r2, r3;
                ldsm_x4(r0, r1, r2, r3, Kt_s + (uint32_t)((nb + kb_nrow)*72 + k0 + kb_koff)*2u);
                mma_f16(s[np*2][0],   s[np*2][1],   s[np*2][2],   s[np*2][3],   a0,a1,a2,a3, r0, r1);
                mma_f16(s[np*2+1][0], s[np*2+1][1], s[np*2+1][2], s[np*2+1][3], a0,a1,a2,a3, r2, r3);
            }
        }
        float mc0 = -INFINITY, mc1 = -INFINITY;
#pragma unroll
        for (int ni = 0; ni < 8; ni++) {
            int colb = kt*64 + ni*8 + 2*tig;
#pragma unroll
            for (int cc = 0; cc < 4; cc++) {
                float v = s[ni][cc] * 0.125f;
                if (colb + (cc & 1) >= N_) v = -INFINITY;
                s[ni][cc] = v;
                if (cc < 2) mc0 = fmaxf(mc0, v); else mc1 = fmaxf(mc1, v);
            }
        }
        mc0 = fmaxf(mc0, __shfl_xor_sync(~0u, mc0, 1));
        mc0 = fmaxf(mc0, __shfl_xor_sync(~0u, mc0, 2));
        mc1 = fmaxf(mc1, __shfl_xor_sync(~0u, mc1, 1));
        mc1 = fmaxf(mc1, __shfl_xor_sync(~0u, mc1, 2));
        float mn0 = fmaxf(mr0, mc0), mn1 = fmaxf(mr1, mc1);
        float al0 = expf(mr0 - mn0), al1 = expf(mr1 - mn1);
        mr0 = mn0; mr1 = mn1;
        float ls0 = 0.f, ls1 = 0.f;
#pragma unroll
        for (int ni = 0; ni < 8; ni++) {
            float p0 = expf(s[ni][0] - mn0);
            float p1 = expf(s[ni][1] - mn0);
            float p2 = expf(s[ni][2] - mn1);
            float p3 = expf(s[ni][3] - mn1);
            s[ni][0]=p0; s[ni][1]=p1; s[ni][2]=p2; s[ni][3]=p3;
            ls0 += p0 + p1; ls1 += p2 + p3;
        }
        ls0 += __shfl_xor_sync(~0u, ls0, 1); ls0 += __shfl_xor_sync(~0u, ls0, 2);
        ls1 += __shfl_xor_sync(~0u, ls1, 1); ls1 += __shfl_xor_sync(~0u, ls1, 2);
        l0 = l0*al0 + ls0; l1 = l1*al1 + ls1;

        __syncwarp();
#pragma unroll
        for (int ni = 0; ni < 8; ni++) {
            *(__half2*)(Pw + g*72     + ni*8 + 2*tig) = __floats2half2_rn(s[ni][0], s[ni][1]);
            *(__half2*)(Pw + (g+8)*72 + ni*8 + 2*tig) = __floats2half2_rn(s[ni][2], s[ni][3]);
        }
#pragma unroll
        for (int ni = 0; ni < 8; ni++) {
            o[ni][0]*=al0; o[ni][1]*=al0; o[ni][2]*=al1; o[ni][3]*=al1;
        }
        __syncwarp();
#pragma unroll
        for (int ks = 0; ks < 4; ks++) {
            int k0 = ks * 16;
            uint32_t a0, a1, a2, a3;
            ldsm_x4(a0, a1, a2, a3, Pw_s + (uint32_t)(a_row*72 + k0 + a_col)*2u);
#pragma unroll
            for (int np = 0; np < 4; np++) {
                int nb = np * 16;
                uint32_t r0, r1, r2, r3;
                ldsm_x4_t(r0, r1, r2, r3, Vt_s + (uint32_t)((k0 + vb_krw)*72 + nb + vb_ncl)*2u);
                mma_f16(o[np*2][0],   o[np*2][1],   o[np*2][2],   o[np*2][3],   a0,a1,a2,a3, r0, r2);
                mma_f16(o[np*2+1][0], o[np*2+1][1], o[np*2+1][2], o[np*2+1][3], a0,a1,a2,a3, r1, r3);
            }
        }
        __syncthreads();
        if (kt + 2 < 8) FA_ISSUE(kt + 2, buf);
    }
#undef FA_ISSUE

    int r0 = q0 + warp*16 + g, r1 = r0 + 8;
    float inv0 = 1.f / l0, inv1 = 1.f / l1;
#pragma unroll
    for (int ni = 0; ni < 8; ni++) {
        int col = h*D_ + ni*8 + 2*tig;
        if (r0 < N_)
            *(__half2*)(obuf + ((size_t)b*N_ + r0)*C_ + col) =
                __floats2half2_rn(o[ni][0]*inv0, o[ni][1]*inv0);
        if (r1 < N_)
            *(__half2*)(obuf + ((size_t)b*N_ + r1)*C_ + col) =
                __floats2half2_rn(o[ni][2]*inv1, o[ni][3]*inv1);
    }
}

// ---------------- cls attention row (fp32 softmax of q-row 0, vectorized fp16 loads) -----
__global__ __launch_bounds__(256)
void cls_kernel(const __half* __restrict__ qkv, float* __restrict__ cls_acc) {
    __shared__ float q0s[64];
    __shared__ float red[8];
    int bh = blockIdx.x;
    int b = bh / H_, h = bh % H_;
    const __half* base = qkv + (size_t)b * N_ * (3*C_) + h * D_;
    int tid = threadIdx.x, lane = tid & 31, warp = tid >> 5;
    if (tid < 64) q0s[tid] = __half2float(base[tid]);
    __syncthreads();

    float sc[2] = {-INFINITY, -INFINITY};
#pragma unroll
    for (int half_ = 0; half_ < 2; half_++) {
        int j = tid + half_*256;
        if (j < N_) {
            const uint4* k4 = (const uint4*)(base + (size_t)j*(3*C_) + C_);
            float a = 0.f;
#pragma unroll
            for (int i = 0; i < 8; i++) {
                uint4 u = k4[i];
                const __half2* hp = (const __half2*)&u;
#pragma unroll
                for (int q = 0; q < 4; q++) {
                    float2 f = __half22float2(hp[q]);
                    a += q0s[i*8 + q*2]*f.x + q0s[i*8 + q*2 + 1]*f.y;
                }
            }
            sc[half_] = a * 0.125f;
        }
    }
    float m = fmaxf(sc[0], sc[1]);
#pragma unroll
    for (int off = 16; off; off >>= 1) m = fmaxf(m, __shfl_xor_sync(~0u, m, off));
    if (lane == 0) red[warp] = m;
    __syncthreads();
    float M = red[0];
#pragma unroll
    for (int i = 1; i < 8; i++) M = fmaxf(M, red[i]);
    __syncthreads();
    float e0 = expf(sc[0] - M), e1 = expf(sc[1] - M);
    float t = e0 + e1;
#pragma unroll
    for (int off = 16; off; off >>= 1) t += __shfl_xor_sync(~0u, t, off);
    if (lane == 0) red[warp] = t;
    __syncthreads();
    float L = 0.f;
#pragma unroll
    for (int i = 0; i < 8; i++) L += red[i];
    float invL = 1.f / (L * (float)H_);
    int j = tid;
    if (j >= 1 && j < N_) atomicAdd(&cls_acc[b*(N_-1) + j - 1], e0 * invL);
    j = tid + 256;
    if (j < N_) atomicAdd(&cls_acc[b*(N_-1) + j - 1], e1 * invL);
}

// ---------------- glb EMA ----------------
__global__ void glb_kernel() {
    int i = blockIdx.x*blockDim.x + threadIdx.x;
    if (i < B_*(N_-1)) {
        g_glb[i] = 0.5f * g_glb[i] + 0.5f * g_cls[i];
        g_cls[i] = 0.f;
    }
}

// ---------------- output ----------------
__global__ void copy_out_kernel(float* __restrict__ out, int out_size) {
    const int NX = B_*N_*C_;
    const int NG = B_*(N_-1);
    for (int i = blockIdx.x*blockDim.x + threadIdx.x; i < out_size;
         i += gridDim.x*blockDim.x) {
        float v = 0.f;
        if (i < NX)            v = g_x[i];
        else if (i < NX + NG)  v = g_glb[i - NX];
        out[i] = v;
    }
}

// ---------------- launch ----------------
extern "C" void kernel_launch(void* const* d_in, const int* in_sizes, int n_in,
                              void* d_out, int out_size) {
    const float* x       = (const float*)d_in[0];
    const float* gattn   = (const float*)d_in[1];
    const float* split_w = (const float*)d_in[2];
    const float* split_b = (const float*)d_in[3];
    const float* ln1_g   = (const float*)d_in[4];
    const float* ln1_b   = (const float*)d_in[5];
    const float* qkv_w   = (const float*)d_in[6];
    const float* qkv_b   = (const float*)d_in[7];
    const float* proj_w  = (const float*)d_in[8];
    const float* proj_b  = (const float*)d_in[9];
    const float* ln2_g   = (const float*)d_in[10];
    const float* ln2_b   = (const float*)d_in[11];
    const float* fc1_w   = (const float*)d_in[12];
    const float* fc1_b   = (const float*)d_in[13];
    const float* fc2_w   = (const float*)d_in[14];
    const float* fc2_b   = (const float*)d_in[15];

    float *px, *pcls;
    __half *ph, *pqkv, *po, *pmlp, *ptok;
    __half *pwsplit, *pwqkv, *pwproj, *pwfc1, *pwfc2;
    cudaGetSymbolAddress((void**)&px,   g_x);
    cudaGetSymbolAddress((void**)&ph,   g_h);
    cudaGetSymbolAddress((void**)&pqkv, g_qkv);
    cudaGetSymbolAddress((void**)&po,   g_o);
    cudaGetSymbolAddress((void**)&pmlp, g_mlp);
    cudaGetSymbolAddress((void**)&ptok, g_tok);
    cudaGetSymbolAddress((void**)&pcls, g_cls);
    cudaGetSymbolAddress((void**)&pwsplit, g_wsplit);
    cudaGetSymbolAddress((void**)&pwqkv,   g_wqkv);
    cudaGetSymbolAddress((void**)&pwproj,  g_wproj);
    cudaGetSymbolAddress((void**)&pwfc1,   g_wfc1);
    cudaGetSymbolAddress((void**)&pwfc2,   g_wfc2);

    cudaFuncSetAttribute(gemm_h,     cudaFuncAttributeMaxDynamicSharedMemorySize, GEMM_SMEM);
    cudaFuncSetAttribute(flash_attn, cudaFuncAttributeMaxDynamicSharedMemorySize, FA_SMEM);

    wconv_kernel<<<2048, 256>>>(split_w, pwsplit, SW_SZ);
    sort_kernel<<<B_, 256>>>(gattn);
    gather_kernel<<<B_*197, 256>>>(x);
    init_kernel<<<(B_*(N_-1) + 255)/256, 256>>>();
    wconv_kernel<<<2048, 256>>>(qkv_w,   pwqkv,   L_*QW_SZ);
    {   // split GEMM  M=1568, N=3072, K=768
        int M = B_*SPLN, N = 4*C_, K = C_;
        dim3 grid(N/128, (M + 127)/128);
        gemm_h<<<grid, 256, GEMM_SMEM>>>(ptok, pwsplit, split_b, nullptr, px, M, N, K, 3);
    }
    wconv_kernel<<<2048, 256>>>(proj_w,  pwproj,  L_*PW_SZ);
    wconv_kernel<<<2048, 256>>>(fc1_w,   pwfc1,   L_*F1_SZ);
    wconv_kernel<<<2048, 256>>>(fc2_w,   pwfc2,   L_*F2_SZ);

    for (int l = 0; l < L_; l++) {
        const float* l1g = ln1_g + l*C_;
        const float* l1b = ln1_b + l*C_;
        const __half* qw = pwqkv + (size_t)l*QW_SZ;
        const float* qb  = qkv_b + l*3*C_;
        const __half* pw = pwproj + (size_t)l*PW_SZ;
        const float* pb  = proj_b + l*C_;
        const float* l2g = ln2_g + l*C_;
        const float* l2b = ln2_b + l*C_;
        const __half* w1 = pwfc1 + (size_t)l*F1_SZ;
        const float* b1  = fc1_b + l*HM_;
        const __half* w2 = pwfc2 + (size_t)l*F2_SZ;
        const float* b2  = fc2_b + l*C_;

        ln_kernel<<<(M_ROWS + 7)/8, 256>>>(px, ph, l1g, l1b);

        { dim3 grid((3*C_)/128, (M_ROWS + 127)/128);
          gemm_h<<<grid, 256, GEMM_SMEM>>>(ph, qw, qb, nullptr, pqkv, M_ROWS, 3*C_, C_, 4); }

        cls_kernel<<<B_*H_, 256>>>(pqkv, pcls);

        { dim3 grid(4, B_*H_);
          flash_attn<<<grid, 256, FA_SMEM>>>(pqkv, po); }

        glb_kernel<<<(B_*(N_-1) + 255)/256, 256>>>();

        { dim3 grid(C_/128, (M_ROWS + 127)/128);
          gemm_h<<<grid, 256, GEMM_SMEM>>>(po, pw, pb, px, px, M_ROWS, C_, C_, 2); }

        ln_kernel<<<(M_ROWS + 7)/8, 256>>>(px, ph, l2g, l2b);

        { dim3 grid(HM_/128, (M_ROWS + 127)/128);
          gemm_h<<<grid, 256, GEMM_SMEM>>>(ph, w1, b1, nullptr, pmlp, M_ROWS, HM_, C_, 1); }

        { dim3 grid(C_/128, (M_ROWS + 127)/128);
          gemm_h<<<grid, 256, GEMM_SMEM>>>(pmlp, w2, b2, px, px, M_ROWS, C_, HM_, 2); }
    }

    copy_out_kernel<<<2048, 256>>>((float*)d_out, out_size);
}

// round 11
// speedup vs baseline: 1.6926x; 1.0072x over previous
#include <cuda_runtime.h>
#include <cuda_fp16.h>
#include <math.h>
#include <stdint.h>

// ---------------- problem constants ----------------
#define B_    16
#define NTOK  196
#define SPLN  98
#define N_    491          // 1 + 98*4 + 98
#define C_    768
#define HM_   3072
#define H_    12
#define D_    64
#define L_    4
#define M_ROWS (B_*N_)     // 7856

// weight sizes
#define SW_SZ   (C_*4*C_)
#define QW_SZ   (C_*3*C_)
#define PW_SZ   (C_*C_)
#define F1_SZ   (C_*HM_)
#define F2_SZ   (HM_*C_)

// ---------------- device scratch ----------------
__device__ float  g_x   [B_*N_*C_];          // residual stream (fp32)
__device__ __half g_h   [B_*N_*C_];          // LN output (fp16)
__device__ __half g_qkv [B_*N_*3*C_];        // qkv (fp16)
__device__ __half g_o   [B_*N_*C_];          // attention output (fp16)
__device__ __half g_mlp [B_*N_*HM_];         // fc1 output (fp16)
__device__ __half g_tok [B_*SPLN*C_];        // gathered top tokens (fp16)
__device__ int    g_ord [B_*NTOK];
__device__ float  g_glb [B_*(N_-1)];
__device__ float  g_cls [B_*(N_-1)];
__device__ float  g_srow[B_*H_*512];         // raw row-0 attention scores (from flash)
// fp16 weights
__device__ __half g_wsplit[SW_SZ];
__device__ __half g_wqkv  [L_*QW_SZ];
__device__ __half g_wproj [L_*PW_SZ];
__device__ __half g_wfc1  [L_*F1_SZ];
__device__ __half g_wfc2  [L_*F2_SZ];

// ---------------- helpers ----------------
__device__ __forceinline__ uint32_t smem_u32(const void* p) {
    uint32_t a;
    asm("{ .reg .u64 t; cvta.to.shared.u64 t, %1; cvt.u32.u64 %0, t; }" : "=r"(a) : "l"(p));
    return a;
}
__device__ __forceinline__ void mma_f16(float& c0, float& c1, float& c2, float& c3,
                                        uint32_t a0, uint32_t a1, uint32_t a2, uint32_t a3,
                                        uint32_t b0, uint32_t b1) {
    asm volatile("mma.sync.aligned.m16n8k16.row.col.f32.f16.f16.f32 "
                 "{%0,%1,%2,%3}, {%4,%5,%6,%7}, {%8,%9}, {%0,%1,%2,%3};"
                 : "+f"(c0), "+f"(c1), "+f"(c2), "+f"(c3)
                 : "r"(a0), "r"(a1), "r"(a2), "r"(a3), "r"(b0), "r"(b1));
}
__device__ __forceinline__ void ldsm_x4(uint32_t& r0, uint32_t& r1, uint32_t& r2, uint32_t& r3,
                                        uint32_t addr) {
    asm volatile("ldmatrix.sync.aligned.m8n8.x4.shared.b16 {%0,%1,%2,%3}, [%4];"
                 : "=r"(r0), "=r"(r1), "=r"(r2), "=r"(r3) : "r"(addr));
}
__device__ __forceinline__ void ldsm_x4_t(uint32_t& r0, uint32_t& r1, uint32_t& r2, uint32_t& r3,
                                          uint32_t addr) {
    asm volatile("ldmatrix.sync.aligned.m8n8.x4.trans.shared.b16 {%0,%1,%2,%3}, [%4];"
                 : "=r"(r0), "=r"(r1), "=r"(r2), "=r"(r3) : "r"(addr));
}
__device__ __forceinline__ void cp16(uint32_t dst, const void* src, int sz) {
    asm volatile("cp.async.cg.shared.global [%0], [%1], 16, %2;"
                 :: "r"(dst), "l"(src), "r"(sz) : "memory");
}
#define CP_COMMIT() asm volatile("cp.async.commit_group;" ::: "memory")
#define CP_WAIT1()  asm volatile("cp.async.wait_group 1;" ::: "memory")
#define CP_WAIT0()  asm volatile("cp.async.wait_group 0;" ::: "memory")

// ---------------- weight convert fp32 -> fp16 ----------------
__global__ void wconv_kernel(const float* __restrict__ src, __half* __restrict__ dst, int n) {
    int stride = gridDim.x * blockDim.x;
    for (int i = blockIdx.x*blockDim.x + threadIdx.x; i < n; i += stride)
        dst[i] = __float2half_rn(src[i]);
}

// ---------------- sort ----------------
__global__ void sort_kernel(const float* __restrict__ attn) {
    __shared__ float sv[256];
    __shared__ int   si[256];
    int b = blockIdx.x, t = threadIdx.x;
    sv[t] = (t < NTOK) ? attn[b*NTOK + t] : -INFINITY;
    si[t] = t;
    __syncthreads();
    for (int k = 2; k <= 256; k <<= 1) {
        for (int j = k >> 1; j > 0; j >>= 1) {
            int ix = t ^ j;
            if (ix > t) {
                float v1 = sv[t], v2 = sv[ix];
                int   i1 = si[t], i2 = si[ix];
                bool before = (v1 > v2) || (v1 == v2 && i1 < i2);
                bool doswap = ((t & k) == 0) ? (!before) : before;
                if (doswap) { sv[t]=v2; sv[ix]=v1; si[t]=i2; si[ix]=i1; }
            }
            __syncthreads();
        }
    }
    if (t < NTOK) g_ord[b*NTOK + t] = si[t];
}

// ---------------- gather ----------------
__global__ void gather_kernel(const float* __restrict__ xin) {
    int blk = blockIdx.x;
    int b = blk / 197, r = blk % 197;
    int t = threadIdx.x;
    if (r == 0) {
        const float* srow = xin + (size_t)b*197*C_;
        float* drow = g_x + (size_t)b*N_*C_;
        drow[t] = srow[t]; drow[t+256] = srow[t+256]; drow[t+512] = srow[t+512];
    } else if (r <= SPLN) {
        int i = r - 1;
        int ord = g_ord[b*NTOK + i];
        const float* srow = xin + ((size_t)b*197 + 1 + ord)*C_;
        __half* drow = g_tok + ((size_t)b*SPLN + i)*C_;
        drow[t]     = __float2half_rn(srow[t]);
        drow[t+256] = __float2half_rn(srow[t+256]);
        drow[t+512] = __float2half_rn(srow[t+512]);
    } else {
        int i = r - 1 - SPLN;
        int ord = g_ord[b*NTOK + SPLN + i];
        const float* srow = xin + ((size_t)b*197 + 1 + ord)*C_;
        float* drow = g_x + ((size_t)b*N_ + 1 + SPLN*4 + i)*C_;
        drow[t] = srow[t]; drow[t+256] = srow[t+256]; drow[t+512] = srow[t+512];
    }
}

__global__ void init_kernel() {
    int i = blockIdx.x*blockDim.x + threadIdx.x;
    if (i < B_*(N_-1)) { g_glb[i] = 0.f; g_cls[i] = 0.f; }
}

// ---------------- fp16 tensor-core GEMM: 128x128 tile, BK=64, warp 64x32, 3-stage cp.async ----
// modes: 0 bias->f32 | 1 bias+gelu->HALF | 2 bias+residual->f32 | 3 bias+split-remap->f32 | 4 bias->HALF
#define A_ST 72
#define W_ST 136
#define A_BY (128*A_ST*2)
#define W_BY (64*W_ST*2)
#define BUF_BY (A_BY + W_BY)
#define NSTAGE 3
#define GEMM_SMEM (NSTAGE*BUF_BY)

__global__ __launch_bounds__(256, 2)
void gemm_h(const __half* __restrict__ A, const __half* __restrict__ W,
            const float* __restrict__ bias, const float* __restrict__ resid,
            void* __restrict__ out, int M, int N, int K, int mode) {
    extern __shared__ char smc[];
    int tid  = threadIdx.x;
    int m0   = blockIdx.y * 128, n0 = blockIdx.x * 128;
    int warp = tid >> 5, lane = tid & 31;
    int g    = lane >> 2, tig = lane & 3;
    int wm0  = (warp >> 2) * 64;
    int wn0  = (warp & 3) * 32;

    uint32_t sbase = smem_u32(smc);

    float acc[4][4][4];
#pragma unroll
    for (int i = 0; i < 4; i++)
#pragma unroll
        for (int j = 0; j < 4; j++)
#pragma unroll
            for (int c = 0; c < 4; c++) acc[i][j][c] = 0.f;

    int nt = K >> 6;

#define ISSUE_TILE(kc_, buf_) do {                                              \
        uint32_t ab = sbase + (uint32_t)(buf_) * BUF_BY;                        \
        uint32_t wb = ab + A_BY;                                               \
        {                                                                       \
            int row = tid >> 1, c = tid & 1;                                    \
            int gr = m0 + row;                                                  \
            int ok = (gr < M);                                                  \
            const __half* src = A + (size_t)(ok ? gr : 0)*K + (kc_)*64 + c*32;  \
            uint32_t d = ab + (uint32_t)row*(A_ST*2) + (uint32_t)c*64;          \
            cp16(d,      src,      ok ? 16 : 0);                                \
            cp16(d + 16, src + 8,  ok ? 16 : 0);                                \
            cp16(d + 32, src + 16, ok ? 16 : 0);                                \
            cp16(d + 48, src + 24, ok ? 16 : 0);                                \
        }                                                                       \
        {                                                                       \
            int kr = tid >> 3, seg = tid & 7;                                   \
            _Pragma("unroll")                                                   \
            for (int rr = 0; rr < 2; rr++) {                                    \
                int r = kr + rr*32;                                             \
                const __half* src = W + (size_t)((kc_)*64 + r)*N + n0 + seg*16; \
                uint32_t d = wb + (uint32_t)r*(W_ST*2) + (uint32_t)seg*32;      \
                cp16(d,      src,     16);                                      \
                cp16(d + 16, src + 8, 16);                                      \
            }                                                                   \
        }                                                                       \
        CP_COMMIT();                                                            \
    } while (0)

    ISSUE_TILE(0, 0);
    ISSUE_TILE(1, 1);

    int a_row = lane & 15;
    int a_col = (lane >> 4) << 3;
    int b_krw = (lane & 7) + (((lane >> 4) & 1) << 3);
    int b_ncl = ((lane >> 3) & 1) << 3;

    for (int kc = 0; kc < nt; kc++) {
        int buf = kc % NSTAGE;
        if (kc == nt - 1) { CP_WAIT0(); } else { CP_WAIT1(); }
        __syncthreads();
        if (kc + 2 < nt) ISSUE_TILE(kc + 2, (kc + 2) % NSTAGE);

        uint32_t ab = sbase + (uint32_t)buf * BUF_BY;
        uint32_t wb = ab + A_BY;
#pragma unroll
        for (int ks = 0; ks < 4; ks++) {
            int k0 = ks * 16;
            uint32_t a[4][4], b[4][2];
#pragma unroll
            for (int mi = 0; mi < 4; mi++) {
                uint32_t addr = ab + (uint32_t)((wm0 + mi*16 + a_row)*A_ST + k0 + a_col)*2;
                ldsm_x4(a[mi][0], a[mi][1], a[mi][2], a[mi][3], addr);
            }
#pragma unroll
            for (int np = 0; np < 2; np++) {
                uint32_t addr = wb + (uint32_t)((k0 + b_krw)*W_ST + wn0 + np*16 + b_ncl)*2;
                uint32_t r0, r1, r2, r3;
                ldsm_x4_t(r0, r1, r2, r3, addr);
                b[np*2][0]   = r0; b[np*2][1]   = r2;
                b[np*2+1][0] = r1; b[np*2+1][1] = r3;
            }
#pragma unroll
            for (int mi = 0; mi < 4; mi++)
#pragma unroll
                for (int ni = 0; ni < 4; ni++)
                    mma_f16(acc[mi][ni][0], acc[mi][ni][1], acc[mi][ni][2], acc[mi][ni][3],
                            a[mi][0], a[mi][1], a[mi][2], a[mi][3],
                            b[ni][0], b[ni][1]);
        }
    }
#undef ISSUE_TILE

    // epilogue
#pragma unroll
    for (int mi = 0; mi < 4; mi++) {
#pragma unroll
        for (int half_ = 0; half_ < 2; half_++) {
            int row = m0 + wm0 + mi*16 + g + half_*8;
            if (row >= M) continue;
#pragma unroll
            for (int ni = 0; ni < 4; ni++) {
                int col = n0 + wn0 + ni*8 + tig*2;
                float v0 = acc[mi][ni][half_*2]     + bias[col];
                float v1 = acc[mi][ni][half_*2 + 1] + bias[col+1];
                if (mode == 1) {
                    v0 = 0.5f*v0*(1.0f + erff(v0*0.70710678118654752f));
                    v1 = 0.5f*v1*(1.0f + erff(v1*0.70710678118654752f));
                    *(__half2*)((__half*)out + (size_t)row*N + col) =
                        __floats2half2_rn(v0, v1);
                } else if (mode == 4) {
                    *(__half2*)((__half*)out + (size_t)row*N + col) =
                        __floats2half2_rn(v0, v1);
                } else if (mode == 2) {
                    const float* rrow = resid + (size_t)row*N;
                    v0 += rrow[col];
                    v1 += rrow[col+1];
                    *(float2*)((float*)out + (size_t)row*N + col) = make_float2(v0, v1);
                } else if (mode == 3) {
                    int bb = row / SPLN, s = row % SPLN;
                    float* orow = (float*)out + ((size_t)bb*N_ + 1 + (size_t)s*4)*C_;
                    *(float2*)(orow + col) = make_float2(v0, v1);
                } else {
                    *(float2*)((float*)out + (size_t)row*N + col) = make_float2(v0, v1);
                }
            }
        }
    }
}

// ---------------- layernorm: warp per row ----------------
__global__ __launch_bounds__(256)
void ln_kernel(const float* __restrict__ in, __half* __restrict__ out,
               const float* __restrict__ gamma, const float* __restrict__ beta) {
    int warp = threadIdx.x >> 5, lane = threadIdx.x & 31;
    int row = blockIdx.x * 8 + warp;
    if (row >= M_ROWS) return;
    const float4* xr = (const float4*)(in + (size_t)row * C_);
    float4 v[6];
    float s = 0.f;
#pragma unroll
    for (int i = 0; i < 6; i++) {
        v[i] = xr[lane + i*32];
        s += v[i].x + v[i].y + v[i].z + v[i].w;
    }
#pragma unroll
    for (int o = 16; o; o >>= 1) s += __shfl_xor_sync(~0u, s, o);
    float mean = s * (1.0f / C_);
    float s2 = 0.f;
#pragma unroll
    for (int i = 0; i < 6; i++) {
        float a = v[i].x - mean, b = v[i].y - mean, c = v[i].z - mean, d = v[i].w - mean;
        s2 += a*a + b*b + c*c + d*d;
    }
#pragma unroll
    for (int o = 16; o; o >>= 1) s2 += __shfl_xor_sync(~0u, s2, o);
    float inv = rsqrtf(s2 * (1.0f / C_) + 1e-6f);
    __half2* orow = (__half2*)(out + (size_t)row * C_);
#pragma unroll
    for (int i = 0; i < 6; i++) {
        int c0 = (lane + i*32) * 4;
        float4 gm = *(const float4*)(gamma + c0);
        float4 bt = *(const float4*)(beta  + c0);
        orow[c0/2]     = __floats2half2_rn((v[i].x - mean)*inv*gm.x + bt.x,
                                           (v[i].y - mean)*inv*gm.y + bt.y);
        orow[c0/2 + 1] = __floats2half2_rn((v[i].z - mean)*inv*gm.z + bt.z,
                                           (v[i].w - mean)*inv*gm.w + bt.w);
    }
}

// ---------------- fp16 flash attention, 128 q-rows per CTA; row-0 scores exported ----------------
#define FA_SMEM 73728
__global__ __launch_bounds__(256)
void flash_attn(const __half* __restrict__ qkv, __half* __restrict__ obuf,
                float* __restrict__ srow_out) {
    extern __shared__ __half sh[];
    __half* Qs = sh;
    __half* Ps = sh + 27648;

    int bh = blockIdx.y;
    int b = bh / H_, h = bh % H_;
    int q0 = blockIdx.x * 128;
    int tid = threadIdx.x, warp = tid >> 5, lane = tid & 31;
    int g = lane >> 2, tig = lane & 3;
    const __half* base = qkv + (size_t)b * N_ * (3*C_) + h * D_;
    uint32_t sb = smem_u32(sh);

    {
        const uint4 z = make_uint4(0,0,0,0);
        for (int idx = tid; idx < 128*8; idx += 256) {
            int r = idx >> 3, c8 = idx & 7;
            int qr = q0 + r;
            uint4 v = z;
            if (qr < N_) v = *(const uint4*)(base + (size_t)qr*(3*C_) + c8*8);
            *(uint4*)(Qs + r*72 + c8*8) = v;
        }
    }

#define FA_ISSUE(kt_, buf_) do {                                              \
        uint32_t kb8 = sb + (uint32_t)(9216 + (buf_)*4608)*2u;                \
        uint32_t vb8 = sb + (uint32_t)(18432 + (buf_)*4608)*2u;               \
        _Pragma("unroll")                                                     \
        for (int it = 0; it < 2; it++) {                                      \
            int chunk = tid + it*256;                                         \
            int r = chunk >> 3, c8 = chunk & 7;                               \
            int kr = (kt_)*64 + r;                                            \
            int ok = (kr < N_);                                               \
            const __half* ksrc = base + (size_t)(ok ? kr : 0)*(3*C_) + C_   + c8*8; \
            const __half* vsrc = base + (size_t)(ok ? kr : 0)*(3*C_) + 2*C_ + c8*8; \
            cp16(kb8 + (uint32_t)(r*72 + c8*8)*2u, ksrc, ok ? 16 : 0);        \
            cp16(vb8 + (uint32_t)(r*72 + c8*8)*2u, vsrc, ok ? 16 : 0);        \
        }                                                                     \
        CP_COMMIT();                                                          \
    } while (0)

    FA_ISSUE(0, 0);
    FA_ISSUE(1, 1);

    float o[8][4];
#pragma unroll
    for (int i = 0; i < 8; i++) { o[i][0]=0.f; o[i][1]=0.f; o[i][2]=0.f; o[i][3]=0.f; }
    float mr0 = -INFINITY, mr1 = -INFINITY, l0 = 0.f, l1 = 0.f;

    __half* Pw = Ps + warp*16*72;

    int a_row = lane & 15;
    int a_col = (lane >> 4) << 3;
    int kb_nrow = (lane & 7) + ((lane >> 4) << 3);
    int kb_koff = ((lane >> 3) & 1) << 3;
    int vb_krw  = (lane & 7) + (((lane >> 4) & 1) << 3);
    int vb_ncl  = ((lane >> 3) & 1) << 3;

    uint32_t Qw_s = sb + (uint32_t)(warp*16*72)*2u;
    uint32_t Pw_s = sb + (uint32_t)(27648 + warp*16*72)*2u;

    bool cls_owner = (q0 == 0) && (warp == 0) && ((lane >> 2) == 0);

    for (int kt = 0; kt < 8; kt++) {
        int buf = kt & 1;
        if (kt == 7) { CP_WAIT0(); } else { CP_WAIT1(); }
        __syncthreads();
        uint32_t Kt_s = sb + (uint32_t)(9216  + buf*4608)*2u;
        uint32_t Vt_s = sb + (uint32_t)(18432 + buf*4608)*2u;

        float s[8][4];
#pragma unroll
        for (int i = 0; i < 8; i++) { s[i][0]=0.f; s[i][1]=0.f; s[i][2]=0.f; s[i][3]=0.f; }
#pragma unroll
        for (int ks = 0; ks < 4; ks++) {
            int k0 = ks * 16;
            uint32_t a0, a1, a2, a3;
            ldsm_x4(a0, a1, a2, a3, Qw_s + (uint32_t)(a_row*72 + k0 + a_col)*2u);
#pragma unroll
            for (int np = 0; np < 4; np++) {
                int nb = np * 16;
                uint32_t r0, r1, r2, r3;
                ldsm_x4(r0, r1, r2, r3, Kt_s + (uint32_t)((nb + kb_nrow)*72 + k0 + kb_koff)*2u);
                mma_f16(s[np*2][0],   s[np*2][1],   s[np*2][2],   s[np*2][3],   a0,a1,a2,a3, r0, r1);
                mma_f16(s[np*2+1][0], s[np*2+1][1], s[np*2+1][2], s[np*2+1][3], a0,a1,a2,a3, r2, r3);
            }
        }
        float mc0 = -INFINITY, mc1 = -INFINITY;
#pragma unroll
        for (int ni = 0; ni < 8; ni++) {
            int colb = kt*64 + ni*8 + 2*tig;
#pragma unroll
            for (int cc = 0; cc < 4; cc++) {
                float v = s[ni][cc] * 0.125f;
                if (colb + (cc & 1) >= N_) v = -INFINITY;
                s[ni][cc] = v;
                if (cc < 2) mc0 = fmaxf(mc0, v); else mc1 = fmaxf(mc1, v);
            }
        }
        // export raw row-0 scores for the cls softmax
        if (cls_owner) {
            float* sr = srow_out + (size_t)bh*512 + kt*64;
#pragma unroll
            for (int ni = 0; ni < 8; ni++) {
                sr[ni*8 + 2*tig]     = s[ni][0];
                sr[ni*8 + 2*tig + 1] = s[ni][1];
            }
        }
        mc0 = fmaxf(mc0, __shfl_xor_sync(~0u, mc0, 1));
        mc0 = fmaxf(mc0, __shfl_xor_sync(~0u, mc0, 2));
        mc1 = fmaxf(mc1, __shfl_xor_sync(~0u, mc1, 1));
        mc1 = fmaxf(mc1, __shfl_xor_sync(~0u, mc1, 2));
        float mn0 = fmaxf(mr0, mc0), mn1 = fmaxf(mr1, mc1);
        float al0 = expf(mr0 - mn0), al1 = expf(mr1 - mn1);
        mr0 = mn0; mr1 = mn1;
        float ls0 = 0.f, ls1 = 0.f;
#pragma unroll
        for (int ni = 0; ni < 8; ni++) {
            float p0 = expf(s[ni][0] - mn0);
            float p1 = expf(s[ni][1] - mn0);
            float p2 = expf(s[ni][2] - mn1);
            float p3 = expf(s[ni][3] - mn1);
            s[ni][0]=p0; s[ni][1]=p1; s[ni][2]=p2; s[ni][3]=p3;
            ls0 += p0 + p1; ls1 += p2 + p3;
        }
        ls0 += __shfl_xor_sync(~0u, ls0, 1); ls0 += __shfl_xor_sync(~0u, ls0, 2);
        ls1 += __shfl_xor_sync(~0u, ls1, 1); ls1 += __shfl_xor_sync(~0u, ls1, 2);
        l0 = l0*al0 + ls0; l1 = l1*al1 + ls1;

        __syncwarp();
#pragma unroll
        for (int ni = 0; ni < 8; ni++) {
            *(__half2*)(Pw + g*72     + ni*8 + 2*tig) = __floats2half2_rn(s[ni][0], s[ni][1]);
            *(__half2*)(Pw + (g+8)*72 + ni*8 + 2*tig) = __floats2half2_rn(s[ni][2], s[ni][3]);
        }
#pragma unroll
        for (int ni = 0; ni < 8; ni++) {
            o[ni][0]*=al0; o[ni][1]*=al0; o[ni][2]*=al1; o[ni][3]*=al1;
        }
        __syncwarp();
#pragma unroll
        for (int ks = 0; ks < 4; ks++) {
            int k0 = ks * 16;
            uint32_t a0, a1, a2, a3;
            ldsm_x4(a0, a1, a2, a3, Pw_s + (uint32_t)(a_row*72 + k0 + a_col)*2u);
#pragma unroll
            for (int np = 0; np < 4; np++) {
                int nb = np * 16;
                uint32_t r0, r1, r2, r3;
                ldsm_x4_t(r0, r1, r2, r3, Vt_s + (uint32_t)((k0 + vb_krw)*72 + nb + vb_ncl)*2u);
                mma_f16(o[np*2][0],   o[np*2][1],   o[np*2][2],   o[np*2][3],   a0,a1,a2,a3, r0, r2);
                mma_f16(o[np*2+1][0], o[np*2+1][1], o[np*2+1][2], o[np*2+1][3], a0,a1,a2,a3, r1, r3);
            }
        }
        __syncthreads();
        if (kt + 2 < 8) FA_ISSUE(kt + 2, buf);
    }
#undef FA_ISSUE

    int r0 = q0 + warp*16 + g, r1 = r0 + 8;
    float inv0 = 1.f / l0, inv1 = 1.f / l1;
#pragma unroll
    for (int ni = 0; ni < 8; ni++) {
        int col = h*D_ + ni*8 + 2*tig;
        if (r0 < N_)
            *(__half2*)(obuf + ((size_t)b*N_ + r0)*C_ + col) =
                __floats2half2_rn(o[ni][0]*inv0, o[ni][1]*inv0);
        if (r1 < N_)
            *(__half2*)(obuf + ((size_t)b*N_ + r1)*C_ + col) =
                __floats2half2_rn(o[ni][2]*inv1, o[ni][3]*inv1);
    }
}

// ---------------- cls softmax over exported row-0 scores ----------------
__global__ __launch_bounds__(512)
void cls2_kernel(const float* __restrict__ srow, float* __restrict__ cls_acc) {
    __shared__ float red[16];
    int bh = blockIdx.x;
    int b = bh / H_;
    int tid = threadIdx.x, lane = tid & 31, warp = tid >> 5;
    float v = (tid < N_) ? srow[(size_t)bh*512 + tid] : -INFINITY;
    float m = v;
#pragma unroll
    for (int o = 16; o; o >>= 1) m = fmaxf(m, __shfl_xor_sync(~0u, m, o));
    if (lane == 0) red[warp] = m;
    __syncthreads();
    float M = red[0];
#pragma unroll
    for (int i = 1; i < 16; i++) M = fmaxf(M, red[i]);
    __syncthreads();
    float e = (tid < N_) ? expf(v - M) : 0.f;
    float t = e;
#pragma unroll
    for (int o = 16; o; o >>= 1) t += __shfl_xor_sync(~0u, t, o);
    if (lane == 0) red[warp] = t;
    __syncthreads();
    float L = 0.f;
#pragma unroll
    for (int i = 0; i < 16; i++) L += red[i];
    if (tid >= 1 && tid < N_)
        atomicAdd(&cls_acc[b*(N_-1) + tid - 1], e / (L * (float)H_));
}

// ---------------- glb EMA ----------------
__global__ void glb_kernel() {
    int i = blockIdx.x*blockDim.x + threadIdx.x;
    if (i < B_*(N_-1)) {
        g_glb[i] = 0.5f * g_glb[i] + 0.5f * g_cls[i];
        g_cls[i] = 0.f;
    }
}

// ---------------- glb output copy ----------------
__global__ void copy_glb_kernel(float* __restrict__ out) {
    int i = blockIdx.x*blockDim.x + threadIdx.x;
    if (i < B_*(N_-1)) out[(size_t)B_*N_*C_ + i] = g_glb[i];
}

// ---------------- launch ----------------
extern "C" void kernel_launch(void* const* d_in, const int* in_sizes, int n_in,
                              void* d_out, int out_size) {
    const float* x       = (const float*)d_in[0];
    const float* gattn   = (const float*)d_in[1];
    const float* split_w = (const float*)d_in[2];
    const float* split_b = (const float*)d_in[3];
    const float* ln1_g   = (const float*)d_in[4];
    const float* ln1_b   = (const float*)d_in[5];
    const float* qkv_w   = (const float*)d_in[6];
    const float* qkv_b   = (const float*)d_in[7];
    const float* proj_w  = (const float*)d_in[8];
    const float* proj_b  = (const float*)d_in[9];
    const float* ln2_g   = (const float*)d_in[10];
    const float* ln2_b   = (const float*)d_in[11];
    const float* fc1_w   = (const float*)d_in[12];
    const float* fc1_b   = (const float*)d_in[13];
    const float* fc2_w   = (const float*)d_in[14];
    const float* fc2_b   = (const float*)d_in[15];

    float *px, *pcls, *psrow;
    __half *ph, *pqkv, *po, *pmlp, *ptok;
    __half *pwsplit, *pwqkv, *pwproj, *pwfc1, *pwfc2;
    cudaGetSymbolAddress((void**)&px,   g_x);
    cudaGetSymbolAddress((void**)&ph,   g_h);
    cudaGetSymbolAddress((void**)&pqkv, g_qkv);
    cudaGetSymbolAddress((void**)&po,   g_o);
    cudaGetSymbolAddress((void**)&pmlp, g_mlp);
    cudaGetSymbolAddress((void**)&ptok, g_tok);
    cudaGetSymbolAddress((void**)&pcls, g_cls);
    cudaGetSymbolAddress((void**)&psrow, g_srow);
    cudaGetSymbolAddress((void**)&pwsplit, g_wsplit);
    cudaGetSymbolAddress((void**)&pwqkv,   g_wqkv);
    cudaGetSymbolAddress((void**)&pwproj,  g_wproj);
    cudaGetSymbolAddress((void**)&pwfc1,   g_wfc1);
    cudaGetSymbolAddress((void**)&pwfc2,   g_wfc2);

    cudaFuncSetAttribute(gemm_h,     cudaFuncAttributeMaxDynamicSharedMemorySize, GEMM_SMEM);
    cudaFuncSetAttribute(flash_attn, cudaFuncAttributeMaxDynamicSharedMemorySize, FA_SMEM);

    wconv_kernel<<<2048, 256>>>(split_w, pwsplit, SW_SZ);
    sort_kernel<<<B_, 256>>>(gattn);
    gather_kernel<<<B_*197, 256>>>(x);
    init_kernel<<<(B_*(N_-1) + 255)/256, 256>>>();
    wconv_kernel<<<2048, 256>>>(qkv_w,   pwqkv,   L_*QW_SZ);
    {   // split GEMM  M=1568, N=3072, K=768
        int M = B_*SPLN, N = 4*C_, K = C_;
        dim3 grid(N/128, (M + 127)/128);
        gemm_h<<<grid, 256, GEMM_SMEM>>>(ptok, pwsplit, split_b, nullptr, px, M, N, K, 3);
    }
    wconv_kernel<<<2048, 256>>>(proj_w,  pwproj,  L_*PW_SZ);
    wconv_kernel<<<2048, 256>>>(fc1_w,   pwfc1,   L_*F1_SZ);
    wconv_kernel<<<2048, 256>>>(fc2_w,   pwfc2,   L_*F2_SZ);

    for (int l = 0; l < L_; l++) {
        const float* l1g = ln1_g + l*C_;
        const float* l1b = ln1_b + l*C_;
        const __half* qw = pwqkv + (size_t)l*QW_SZ;
        const float* qb  = qkv_b + l*3*C_;
        const __half* pw = pwproj + (size_t)l*PW_SZ;
        const float* pb  = proj_b + l*C_;
        const float* l2g = ln2_g + l*C_;
        const float* l2b = ln2_b + l*C_;
        const __half* w1 = pwfc1 + (size_t)l*F1_SZ;
        const float* b1  = fc1_b + l*HM_;
        const __half* w2 = pwfc2 + (size_t)l*F2_SZ;
        const float* b2  = fc2_b + l*C_;

        ln_kernel<<<(M_ROWS + 7)/8, 256>>>(px, ph, l1g, l1b);

        { dim3 grid((3*C_)/128, (M_ROWS + 127)/128);
          gemm_h<<<grid, 256, GEMM_SMEM>>>(ph, qw, qb, nullptr, pqkv, M_ROWS, 3*C_, C_, 4); }

        { dim3 grid(4, B_*H_);
          flash_attn<<<grid, 256, FA_SMEM>>>(pqkv, po, psrow); }

        cls2_kernel<<<B_*H_, 512>>>(psrow, pcls);

        glb_kernel<<<(B_*(N_-1) + 255)/256, 256>>>();

        { dim3 grid(C_/128, (M_ROWS + 127)/128);
          gemm_h<<<grid, 256, GEMM_SMEM>>>(po, pw, pb, px, px, M_ROWS, C_, C_, 2); }

        ln_kernel<<<(M_ROWS + 7)/8, 256>>>(px, ph, l2g, l2b);

        { dim3 grid(HM_/128, (M_ROWS + 127)/128);
          gemm_h<<<grid, 256, GEMM_SMEM>>>(ph, w1, b1, nullptr, pmlp, M_ROWS, HM_, C_, 1); }

        {   // fc2: final layer writes x directly into d_out
            float* xdst = (l == L_ - 1) ? (float*)d_out : px;
            dim3 grid(C_/128, (M_ROWS + 127)/128);
            gemm_h<<<grid, 256, GEMM_SMEM>>>(pmlp, w2, b2, px, xdst, M_ROWS, C_, HM_, 2);
        }
    }

    copy_glb_kernel<<<(B_*(N_-1) + 255)/256, 256>>>((float*)d_out);
}